// round 12
// baseline (speedup 1.0000x reference)
#include <cuda_runtime.h>

#define PI_F 3.14159265358979323846f

// exact compile-time twiddles (roots of unity for N=12 and N=6)
#define SQ3_2 0.86602540378443864676f
static __device__ constexpr float CE12X[12] = {1.f, SQ3_2, .5f, 0.f, -.5f, -SQ3_2, -1.f, -SQ3_2, -.5f, 0.f, .5f, SQ3_2};
static __device__ constexpr float CE12Y[12] = {0.f, .5f, SQ3_2, 1.f, SQ3_2, .5f, 0.f, -.5f, -SQ3_2, -1.f, -SQ3_2, -.5f};
static __device__ constexpr float CE6X[6]   = {1.f, .5f, -.5f, -1.f, -.5f, .5f};
static __device__ constexpr float CE6Y[6]   = {0.f, SQ3_2, SQ3_2, 0.f, -SQ3_2, -SQ3_2};
__host__ __device__ constexpr int md(int x, int m) { return ((x % m) + m) % m; }
__host__ __device__ constexpr int COFF(int mq) { return mq*6 - mq*(mq-1)/2; }  // 0,6,11,15,18,20

__constant__ float C_FACTF[11] = {1.f,1.f,2.f,6.f,24.f,120.f,720.f,5040.f,
                                  40320.f,362880.f,3628800.f};
__constant__ int C_MQ[21] = {0,0,0,0,0,0, 1,1,1,1,1, 2,2,2,2, 3,3,3, 4,4, 5};
__constant__ int C_L [21] = {0,1,2,3,4,5, 1,2,3,4,5, 2,3,4,5, 3,4,5, 4,5, 5};

__device__ float  g_w_l2[6];
__device__ float2 g_e20[20];
__device__ __align__(16) float  g_DS2 [1320];   // [l6][k20][m'+5]  (quad-weighted)
__device__ __align__(16) float  g_TD1C[5184];   // [l6][k12][mq6][j12 pad] *(2l+1), m'>=0 only
__device__ __align__(16) float  g_DSO3[900];    // [l3][k12][m2+2][p2+2] *w
__device__ __align__(16) float  g_TD2 [450];    // [l3][k6][m2+2][p2+2] *(2l+1)
__device__ __align__(16) float2 g_PSI1[1584];   // [l6][g24][m'+5]
__device__ __align__(16) float2 g_PSI2[10800];  // [l3][g144][m+2][p+2]
__device__ __align__(16) float2 g_CY1 [528];    // [l6][o8][p'+5]
__device__ __align__(16) float2 g_CY2 [9600];   // [l3][f8][o16][j2+2][k2+2]
__device__ float  g_feat[2048*16];
__device__ unsigned g_ctr;

__device__ float wig_df(int l, int mp, int m, float beta) {
    if (mp < -l || mp > l || m < -l || m > l) return 0.f;
    float c = cosf(0.5f*beta), s = sinf(0.5f*beta);
    int k0 = max(0, m - mp), k1 = min(l + m, l - mp);
    if (k1 < k0) return 0.f;
    float pre = sqrtf(C_FACTF[l+mp]*C_FACTF[l-mp]*C_FACTF[l+m]*C_FACTF[l-m]);
    float acc = 0.f;
    for (int k = k0; k <= k1; k++) {
        float t = pre/(C_FACTF[l+m-k]*C_FACTF[k]*C_FACTF[mp-m+k]*C_FACTF[l-mp-k]);
        int ec = 2*l - 2*k + m - mp, es = mp - m + 2*k;
        float pc = 1.f, ps = 1.f;
        for (int i = 0; i < ec; i++) pc *= c;
        for (int i = 0; i < es; i++) ps *= s;
        acc += (((mp - m + k) & 1) ? -t : t) * pc * ps;
    }
    return acc;
}

__device__ float quad_w(int k, int b) {   // Driscoll-Healy weight, fp32
    float beta = PI_F*(2*k+1)/(4.0f*b), ss = 0.f;
    for (int j = 0; j < b; j++) ss += sinf((2*j+1)*beta)/(float)(2*j+1);
    return (2.0f/b)*sinf(beta)*ss;
}

__global__ void k_tables() {
    const int N0=1320, N1=5184, N2=900, N3=450, N4=1584, N5=10800, N6=26;
    int stride = gridDim.x * blockDim.x;
    for (int e = blockIdx.x*blockDim.x + threadIdx.x; e < N0+N1+N2+N3+N4+N5+N6; e += stride) {
        int i = e;
        if (i < N0) {
            int j = i%11, k = (i/11)%20, l = i/220;
            g_DS2[i] = wig_df(l, j-5, 0, PI_F*(2*k+1)/40.0f) * quad_w(k, 10);
            continue;
        }
        i -= N0;
        if (i < N1) {  // TD1C[l][k][mq][j12]
            int j = i%12, mq = (i/12)%6, k = (i/72)%12, l = i/864;
            g_TD1C[i] = (j < 11) ? (float)(2*l+1)*wig_df(l, mq, j-5, PI_F*(2*k+1)/24.0f) : 0.f;
            continue;
        }
        i -= N1;
        if (i < N2) {
            int j = i%5, mi = (i/5)%5, k = (i/25)%12, l = i/300;
            g_DSO3[i] = wig_df(l, mi-2, j-2, PI_F*(2*k+1)/24.0f) * quad_w(k, 6);
            continue;
        }
        i -= N2;
        if (i < N3) {
            int j = i%5, mi = (i/5)%5, k = (i/25)%6, l = i/150;
            g_TD2[i] = (float)(2*l+1) * wig_df(l, mi-2, j-2, PI_F*(2*k+1)/12.0f);
            continue;
        }
        i -= N3;
        if (i < N4) {
            int j = i%11, g = (i/11)%24, l = i/264;
            int mp = j - 5;
            float b  = (float)(g/8 + 1) * (PI_F/24.0f);
            float al = (float)(g%8) * (PI_F/4.0f);
            float d  = wig_df(l, mp, 0, b);
            float ang = -(float)mp * al;
            g_PSI1[i] = make_float2(d*cosf(ang), d*sinf(ang));
            continue;
        }
        i -= N4;
        if (i < N5) {
            int j = i%5, mi = (i/5)%5, g = (i/25)%144, l = i/3600;
            int m = mi - 2, p = j - 2;
            float b  = (float)(g/48 + 1) * (PI_F/24.0f);
            float al = (float)((g/6)%8) * (PI_F/4.0f);
            float ga = (float)(g%6) * (PI_F/3.0f);
            float d  = wig_df(l, m, p, b);
            float ang = -((float)m*al + (float)p*ga);
            g_PSI2[i] = make_float2(d*cosf(ang), d*sinf(ang));
            continue;
        }
        i -= N5;
        if (i < 20)      { float a = 2.0f*PI_F*i/20.0f; g_e20[i] = make_float2(cosf(a), sinf(a)); }
        else             g_w_l2[i-20] = quad_w(i-20, 3);
    }
}

__global__ void k_weights(const float* __restrict__ w1, const float* __restrict__ w2) {
    const int NC1 = 528, NC2 = 9600;
    int stride = gridDim.x * blockDim.x;
    for (int e = blockIdx.x*blockDim.x + threadIdx.x; e < NC1+NC2; e += stride) {
        if (e < NC1) {
            int j = e%11, o = (e/11)%8, l = e/88;
            float re = 0.f, im = 0.f;
            for (int g = 0; g < 24; g++) {
                float wv = w1[o*24 + g];
                float2 ps = g_PSI1[(l*24 + g)*11 + j];
                re += wv*ps.x; im += wv*ps.y;
            }
            g_CY1[e] = make_float2(re, -im);
        } else {
            int i = e - NC1;
            int k2 = i%5, j2 = (i/5)%5, o = (i/25)%16, f = (i/400)%8, l = i/3200;
            float re = 0.f, im = 0.f;
            for (int g = 0; g < 144; g++) {
                float wv = w2[(f*16 + o)*144 + g];
                float2 ps = g_PSI2[((l*144 + g)*5 + j2)*5 + k2];
                re += wv*ps.x; im += wv*ps.y;
            }
            g_CY2[i] = make_float2(re, -im);
        }
    }
}

__device__ __forceinline__ float2 cfma(float2 a, float2 b, float2 c) {
    c.x += a.x*b.x - a.y*b.y;
    c.y += a.x*b.y + a.y*b.x;
    return c;
}
__device__ __forceinline__ void cfmac(float2 f, float wx, float wy, float2& c) {
    c.x += f.x*wx - f.y*wy;
    c.y += f.x*wy + f.y*wx;
}

// smem: misc[0..256) | R1 region [256..4288) | G region [4288..18112)
#define SM_FLOATS 18112
#define SM_BYTES  (SM_FLOATS*4)

// Ph4+5 body: jacc = sum_{l>=MQ} TD1C*P2, then radix-2 gamma synthesis -> G
template<int MQ>
__device__ __forceinline__ void ph45(const float2* __restrict__ P2, float2* __restrict__ G,
                                     int o, int kk) {
    float2 jacc[12];
    #pragma unroll
    for (int j = 0; j < 12; j++) jacc[j] = make_float2(0.f, 0.f);
    #pragma unroll
    for (int l = MQ; l < 6; l++) {
        const float4* dp4 = (const float4*)(g_TD1C + ((l*12 + kk)*6 + MQ)*12);
        const float4* pp4 = (const float4*)(P2 + ((COFF(MQ) + (l - MQ))*8 + o)*12);
        #pragma unroll
        for (int q = 0; q < 3; q++) {
            float4 d  = dp4[q];
            float4 pa = pp4[2*q], pb = pp4[2*q+1];
            jacc[4*q+0].x += d.x*pa.x; jacc[4*q+0].y += d.x*pa.y;
            jacc[4*q+1].x += d.y*pa.z; jacc[4*q+1].y += d.y*pa.w;
            jacc[4*q+2].x += d.z*pb.x; jacc[4*q+2].y += d.z*pb.y;
            jacc[4*q+3].x += d.w*pb.z; jacc[4*q+3].y += d.w*pb.w;
        }
    }
    float2* gp = G + ((o*12 + kk)*6 + MQ)*12;
    #pragma unroll
    for (int g1 = 0; g1 < 6; g1++) {
        float2 Se = make_float2(0.f, 0.f), So = make_float2(0.f, 0.f);
        #pragma unroll
        for (int j = 1; j < 11; j += 2)   // p' even
            cfmac(jacc[j], CE12X[md((j-5)*g1,12)], CE12Y[md((j-5)*g1,12)], Se);
        #pragma unroll
        for (int j = 0; j < 11; j += 2)   // p' odd
            cfmac(jacc[j], CE12X[md((j-5)*g1,12)], CE12Y[md((j-5)*g1,12)], So);
        gp[g1]     = make_float2(Se.x + So.x, Se.y + So.y);
        gp[g1 + 6] = make_float2(Se.x - So.x, Se.y - So.y);
    }
}

__global__ void __launch_bounds__(512, 3)
k_forward(const float* __restrict__ x, const float* __restrict__ b1,
          const float* __restrict__ b2, const float* __restrict__ w_out,
          const float* __restrict__ b_out, float* __restrict__ out) {
    extern __shared__ float sm[];
    float2* se20 = (float2*)(sm);        // 20c
    float*  sb1  = sm + 76;              // 8
    float*  sb2  = sm + 84;              // 16
    float*  swi  = sm + 100;             // 6
    float2* sXS  = (float2*)(sm + 108);  // 66c
    float*  R1   = sm + 256;             // 4032 floats (P2 / h1q / F2h / h2 / final)
    float2* G    = (float2*)(sm + 4288); // 6912 c2 = 13824 floats
    __shared__ unsigned s_last;

    const int tid = threadIdx.x;
    const int n = blockIdx.x;

    if (tid < 20)                se20[tid]     = g_e20[tid];
    if (tid >= 96  && tid < 104) sb1 [tid-96]  = b1[tid-96];
    if (tid >= 128 && tid < 144) sb2 [tid-128] = b2[tid-128];
    if (tid >= 160 && tid < 166) swi [tid-160] = g_w_l2[tid-160] * (1.f/36.f);

    // Ph0: load x[n] (20x20) into R1
    float* sx = R1;
    for (int i = tid; i < 400; i += 512) sx[i] = x[n*400 + i];
    __syncthreads();

    // Ph1: alpha analysis Xf[k][m'+5] -> G region
    float2* Xf = G;
    if (tid < 220) {
        int k = tid/11, mp = tid%11 - 5;
        int s = (20 - mp) % 20;
        const float* xp = sx + k*20;
        float re = 0.f, im = 0.f;
        int r = 0;
        #pragma unroll
        for (int a = 0; a < 20; a++) {
            float v = xp[a];
            float2 w = se20[r];
            re += v*w.x; im += v*w.y;
            r += s; if (r >= 20) r -= 20;
        }
        Xf[tid] = make_float2(re, im);
    }
    __syncthreads();

    // Ph2: XS[l][m'+5] = sum_k DS2 * Xf
    if (tid < 66) {
        int l = tid/11, j = tid%11;
        float2 acc = make_float2(0.f, 0.f);
        #pragma unroll
        for (int k = 0; k < 20; k++) {
            float d = g_DS2[(l*20 + k)*11 + j];
            float2 v = Xf[k*11 + j];
            acc.x += d*v.x; acc.y += d*v.y;
        }
        sXS[tid] = acc;
    }
    __syncthreads();

    // Ph3: packed P2[pidx(l,mq)][o][j12] = XS * CY1  (R1, sx dead). 168 threads.
    float2* P2 = (float2*)R1;
    if (tid < 168) {
        int pidx = tid % 21, o = tid / 21;
        int l = C_L[pidx], mq = C_MQ[pidx];
        float2 xs = sXS[l*11 + mq + 5];
        const float2* cy = g_CY1 + (l*8 + o)*11;
        float2* op = P2 + (pidx*8 + o)*12;
        #pragma unroll
        for (int j = 0; j < 11; j++) {
            float2 c = cy[j];
            op[j] = make_float2(xs.x*c.x - xs.y*c.y, xs.x*c.y + xs.y*c.x);
        }
        op[11] = make_float2(0.f, 0.f);
    }
    __syncthreads();

    // Ph4+5 fused (templated on warp-uniform mq): -> G (Xf dead)
    for (int t = tid; t < 576; t += 512) {
        int mq = t / 96;
        int r  = t % 96;
        int o  = r / 12, kk = r % 12;
        switch (mq) {
            case 0: ph45<0>(P2, G, o, kk); break;
            case 1: ph45<1>(P2, G, o, kk); break;
            case 2: ph45<2>(P2, G, o, kk); break;
            case 3: ph45<3>(P2, G, o, kk); break;
            case 4: ph45<4>(P2, G, o, kk); break;
            default: ph45<5>(P2, G, o, kk); break;
        }
    }
    __syncthreads();

    // Ph6+7 chunked over f-pairs: h1 chunk bounces through R1; T[f] overwrites G[f].
    float* hq = R1;
    #pragma unroll
    for (int fc = 0; fc < 4; fc++) {
        // Ph6 chunk: 576 work items on 512 threads (FIX: loop, not guard)
        for (int t = tid; t < 576; t += 512) {
            int ah = t & 1;
            int rest = t >> 1;              // 0..287
            int g = rest % 12, kk = (rest/12) % 12, fo = rest/144;
            int f = fc*2 + fo;
            const float2* Gp = G + ((f*12 + kk)*6)*12 + g;
            float2 gm1 = Gp[12], gm2 = Gp[24], gm3 = Gp[36], gm4 = Gp[48], gm5 = Gp[60];
            float g0 = Gp[0].x;
            float bb = sb1[f];
            float* op = hq + ((fo*12 + kk)*12)*12 + g;
            int a1lo = ah*3;
            #pragma unroll
            for (int d1 = 0; d1 < 3; d1++) {
                int a1 = a1lo + d1;
                float E = g0
                    + 2.f*(gm2.x*CE12X[md(2*a1,12)] - gm2.y*CE12Y[md(2*a1,12)])
                    + 2.f*(gm4.x*CE12X[md(4*a1,12)] - gm4.y*CE12Y[md(4*a1,12)]);
                float O =
                      2.f*(gm1.x*CE12X[md(a1,12)]   - gm1.y*CE12Y[md(a1,12)])
                    + 2.f*(gm3.x*CE12X[md(3*a1,12)] - gm3.y*CE12Y[md(3*a1,12)])
                    + 2.f*(gm5.x*CE12X[md(5*a1,12)] - gm5.y*CE12Y[md(5*a1,12)]);
                op[a1*12]       = fmaxf(E + O + bb, 0.f);
                op[(a1 + 6)*12] = fmaxf(E - O + bb, 0.f);
            }
        }
        __syncthreads();
        // Ph7 chunk: gamma analysis, radix-2 in g; T[f] written into G[f] slot
        if (tid < 288) {
            int a = tid % 12, kk = (tid/12) % 12, fo = tid/144;
            int f = fc*2 + fo;
            const float4* hp4 = (const float4*)(hq + ((fo*12 + kk)*12 + a)*12);
            float h[12];
            #pragma unroll
            for (int q = 0; q < 3; q++) {
                float4 v = hp4[q];
                h[4*q] = v.x; h[4*q+1] = v.y; h[4*q+2] = v.z; h[4*q+3] = v.w;
            }
            float he[6], ho[6];
            #pragma unroll
            for (int g1 = 0; g1 < 6; g1++) { he[g1] = h[g1] + h[g1+6]; ho[g1] = h[g1] - h[g1+6]; }
            float2* op = G + f*864 + (kk*12 + a)*3;
            op[0] = make_float2(he[0]+he[1]+he[2]+he[3]+he[4]+he[5], 0.f);
            {
                float re = 0.f, im = 0.f;
                #pragma unroll
                for (int g1 = 0; g1 < 6; g1++) {
                    re += ho[g1]*CE12X[g1];
                    im -= ho[g1]*CE12Y[g1];
                }
                op[1] = make_float2(re, im);
            }
            {
                float re = 0.f, im = 0.f;
                #pragma unroll
                for (int g1 = 0; g1 < 6; g1++) {
                    re += he[g1]*CE12X[md(2*g1,12)];
                    im -= he[g1]*CE12Y[md(2*g1,12)];
                }
                op[2] = make_float2(re, im);
            }
        }
        __syncthreads();
    }

    // Ph8: alpha analysis F2h[f][kk][m2][p2+2] (R1), m2 warp-uniform, radix-2 in a.
    float2* F2h = (float2*)R1;
    if (tid < 288) {
        int m2 = tid / 96;
        int r  = tid % 96;
        int f = r / 12, kk = r % 12;
        const float2* Tp = G + f*864 + kk*36;
        float2 acc[5];
        #pragma unroll
        for (int j = 0; j < 5; j++) acc[j] = make_float2(0.f, 0.f);
        if (m2 == 0) {
            #pragma unroll
            for (int a1 = 0; a1 < 6; a1++) {
                float2 t0 = Tp[a1*3+0], t1 = Tp[a1*3+1], t2 = Tp[a1*3+2];
                float2 u0 = Tp[(a1+6)*3+0], u1 = Tp[(a1+6)*3+1], u2 = Tp[(a1+6)*3+2];
                t0.x += u0.x; t0.y += u0.y;
                t1.x += u1.x; t1.y += u1.y;
                t2.x += u2.x; t2.y += u2.y;
                acc[0].x += t2.x; acc[0].y -= t2.y;
                acc[1].x += t1.x; acc[1].y -= t1.y;
                acc[2].x += t0.x; acc[2].y += t0.y;
                acc[3].x += t1.x; acc[3].y += t1.y;
                acc[4].x += t2.x; acc[4].y += t2.y;
            }
        } else if (m2 == 1) {
            #pragma unroll
            for (int a1 = 0; a1 < 6; a1++) {
                float2 t0 = Tp[a1*3+0], t1 = Tp[a1*3+1], t2 = Tp[a1*3+2];
                float2 u0 = Tp[(a1+6)*3+0], u1 = Tp[(a1+6)*3+1], u2 = Tp[(a1+6)*3+2];
                t0.x -= u0.x; t0.y -= u0.y;
                t1.x -= u1.x; t1.y -= u1.y;
                t2.x -= u2.x; t2.y -= u2.y;
                const float wx = CE12X[md(-a1,12)], wy = CE12Y[md(-a1,12)];
                cfmac(make_float2(t2.x, -t2.y), wx, wy, acc[0]);
                cfmac(make_float2(t1.x, -t1.y), wx, wy, acc[1]);
                cfmac(t0, wx, wy, acc[2]);
                cfmac(t1, wx, wy, acc[3]);
                cfmac(t2, wx, wy, acc[4]);
            }
        } else {
            #pragma unroll
            for (int a1 = 0; a1 < 6; a1++) {
                float2 t0 = Tp[a1*3+0], t1 = Tp[a1*3+1], t2 = Tp[a1*3+2];
                float2 u0 = Tp[(a1+6)*3+0], u1 = Tp[(a1+6)*3+1], u2 = Tp[(a1+6)*3+2];
                t0.x += u0.x; t0.y += u0.y;
                t1.x += u1.x; t1.y += u1.y;
                t2.x += u2.x; t2.y += u2.y;
                const float wx = CE12X[md(-2*a1,12)], wy = CE12Y[md(-2*a1,12)];
                cfmac(make_float2(t2.x, -t2.y), wx, wy, acc[0]);
                cfmac(make_float2(t1.x, -t1.y), wx, wy, acc[1]);
                cfmac(t0, wx, wy, acc[2]);
                cfmac(t1, wx, wy, acc[3]);
                cfmac(t2, wx, wy, acc[4]);
            }
        }
        float2* op = F2h + ((f*12 + kk)*3 + m2)*5;
        #pragma unroll
        for (int j = 0; j < 5; j++) op[j] = acc[j];
    }
    __syncthreads();

    // Ph9: XS2[l][f][m2][k2] = sum_k F2h * DSO3  -> G base (T dead). 360 threads.
    float2* XS2 = G;
    if (tid < 360) {
        int k2 = tid % 5;
        int rr = tid / 5;
        int m2q = rr % 3, f = (rr/3) % 8, l = rr/24;
        float2 acc = make_float2(0.f, 0.f);
        #pragma unroll
        for (int k = 0; k < 12; k++) {
            float d = g_DSO3[((l*12 + k)*5 + (m2q+2))*5 + k2];
            float2 v = F2h[((f*12 + k)*3 + m2q)*5 + k2];
            acc.x += d*v.x; acc.y += d*v.y;
        }
        XS2[(l*8 + f)*15 + m2q*5 + k2] = acc;
    }
    __syncthreads();

    // Ph10: Z2[l][o][m2][j2] at G+384. 2 units of 15 lanes/warp, k2-sum in regs.
    float2* Z2 = G + 384;
    {
        int w = tid >> 5, lane = tid & 31;
        int half = lane >> 4;
        int sl = lane & 15;
        int q = sl / 5, j2 = sl % 5;
        #pragma unroll
        for (int it = 0; it < 2; it++) {
            int unit = it*32 + w*2 + half;    // 0..63
            if (unit < 48 && sl < 15) {
                int l = unit >> 4, o = unit & 15;
                float2 acc = make_float2(0.f, 0.f);
                #pragma unroll
                for (int f = 0; f < 8; f++) {
                    const float2* xb = XS2 + (l*8 + f)*15 + q*5;
                    const float2* cp = g_CY2 + (((l*8 + f)*16 + o)*5 + j2)*5;
                    #pragma unroll
                    for (int k2 = 0; k2 < 5; k2++)
                        acc = cfma(xb[k2], cp[k2], acc);
                }
                Z2[((l*16 + o)*3 + q)*5 + j2] = acc;
            }
        }
    }
    __syncthreads();

    // Ph11 fused: jacc = sum_{l>=mq} TD2*Z2, radix-2 gamma synthesis -> G2 at G+1152
    float2* G2 = G + 1152;
    if (tid < 288) {
        int mq = tid / 96;
        int r  = tid % 96;
        int o  = r / 6, kk = r % 6;
        float2 jacc[5];
        #pragma unroll
        for (int j = 0; j < 5; j++) jacc[j] = make_float2(0.f, 0.f);
        for (int l = mq; l < 3; l++) {
            const float* dp = g_TD2 + ((l*6 + kk)*5 + (mq+2))*5;
            const float2* zp = Z2 + ((l*16 + o)*3 + mq)*5;
            #pragma unroll
            for (int j = 0; j < 5; j++) {
                float d = dp[j];
                jacc[j].x += d*zp[j].x; jacc[j].y += d*zp[j].y;
            }
        }
        float2* gp = G2 + ((o*6 + kk)*3 + mq)*6;
        #pragma unroll
        for (int g1 = 0; g1 < 3; g1++) {
            float2 Se = make_float2(0.f, 0.f), So = make_float2(0.f, 0.f);
            cfmac(jacc[0], CE6X[md(-2*g1,6)], CE6Y[md(-2*g1,6)], Se);
            Se.x += jacc[2].x; Se.y += jacc[2].y;
            cfmac(jacc[4], CE6X[md(2*g1,6)], CE6Y[md(2*g1,6)], Se);
            cfmac(jacc[1], CE6X[md(-g1,6)], CE6Y[md(-g1,6)], So);
            cfmac(jacc[3], CE6X[md(g1,6)],  CE6Y[md(g1,6)],  So);
            gp[g1]     = make_float2(Se.x + So.x, Se.y + So.y);
            gp[g1 + 3] = make_float2(Se.x - So.x, Se.y - So.y);
        }
    }
    __syncthreads();

    // Ph12: alpha synthesis (Hermitian) + bias + ReLU, pre-weighted -> h2 (R1)
    float* h2 = R1;
    for (int t = tid; t < 576; t += 512) {
        int g = t % 6, kk = (t/6) % 6, o = t/36;
        const float2* Gp = G2 + (o*6 + kk)*18 + g;
        float2 g0 = Gp[0], g1 = Gp[6], g2 = Gp[12];
        float g1x = 2.f*g1.x, g1y = 2.f*g1.y, g2x = 2.f*g2.x, g2y = 2.f*g2.y;
        float bb = sb2[o];
        float wk = swi[kk];
        float* op = h2 + ((o*6 + kk)*6)*6 + g;
        #pragma unroll
        for (int a = 0; a < 6; a++) {
            float v = g0.x + g1x*CE6X[md(a,6)] - g1y*CE6Y[md(a,6)]
                           + g2x*CE6X[md(2*a,6)] - g2y*CE6Y[md(2*a,6)];
            op[a*6] = fmaxf(v + bb, 0.f) * wk;
        }
    }
    __syncthreads();

    // Ph13: integrate: feat[n][o] = sum over pre-weighted h2
    {
        int w = tid >> 5, lane = tid & 31;
        const float* hp = h2 + w*216;
        float s = 0.f;
        #pragma unroll
        for (int idx = lane; idx < 216; idx += 32)
            s += hp[idx];
        #pragma unroll
        for (int off = 16; off; off >>= 1)
            s += __shfl_down_sync(0xffffffffu, s, off);
        if (lane == 0) g_feat[n*16 + w] = s;
    }

    // Fused final: last CTA does maxpool + linear
    __threadfence();
    __syncthreads();
    if (tid == 0) {
        unsigned old = atomicAdd(&g_ctr, 1u);
        s_last = (old == (unsigned)(gridDim.x - 1)) ? 1u : 0u;
    }
    __syncthreads();
    if (s_last) {
        __threadfence();
        float* sp = R1;
        float* pooled = R1 + 512;
        for (int b = 0; b < 4; b++) {
            int o = tid & 15, grp = tid >> 4;
            float m = -3.4e38f;
            #pragma unroll
            for (int j = 0; j < 16; j++) {
                int p = grp + j*32;
                m = fmaxf(m, g_feat[(b*512 + p)*16 + o]);
            }
            sp[grp*16 + o] = m;
            __syncthreads();
            if (tid < 16) {
                float mm = sp[tid];
                for (int g2 = 1; g2 < 32; g2++) mm = fmaxf(mm, sp[g2*16 + tid]);
                pooled[tid] = mm;
            }
            __syncthreads();
            if (tid < 10) {
                float acc = b_out[tid];
                #pragma unroll
                for (int o2 = 0; o2 < 16; o2++) acc += pooled[o2]*w_out[tid*16 + o2];
                out[b*10 + tid] = acc;
            }
            __syncthreads();
        }
        if (tid == 0) g_ctr = 0;
    }
}

extern "C" void kernel_launch(void* const* d_in, const int* in_sizes, int n_in,
                              void* d_out, int out_size) {
    const float* x     = (const float*)d_in[0];
    const float* w1    = (const float*)d_in[1];
    const float* b1    = (const float*)d_in[2];
    const float* w2    = (const float*)d_in[3];
    const float* b2    = (const float*)d_in[4];
    const float* w_out = (const float*)d_in[5];
    const float* b_out = (const float*)d_in[6];
    float* out = (float*)d_out;

    cudaFuncSetAttribute(k_forward, cudaFuncAttributeMaxDynamicSharedMemorySize, SM_BYTES);

    k_tables<<<48, 512>>>();
    k_weights<<<20, 512>>>(w1, w2);
    k_forward<<<2048, 512, SM_BYTES>>>(x, b1, b2, w_out, b_out, out);
}

// round 14
// speedup vs baseline: 1.3502x; 1.3502x over previous
#include <cuda_runtime.h>

#define PI_F 3.14159265358979323846f

// exact compile-time twiddles (roots of unity for N=12 and N=6)
#define SQ3_2 0.86602540378443864676f
static __device__ constexpr float CE12X[12] = {1.f, SQ3_2, .5f, 0.f, -.5f, -SQ3_2, -1.f, -SQ3_2, -.5f, 0.f, .5f, SQ3_2};
static __device__ constexpr float CE12Y[12] = {0.f, .5f, SQ3_2, 1.f, SQ3_2, .5f, 0.f, -.5f, -SQ3_2, -1.f, -SQ3_2, -.5f};
static __device__ constexpr float CE6X[6]   = {1.f, .5f, -.5f, -1.f, -.5f, .5f};
static __device__ constexpr float CE6Y[6]   = {0.f, SQ3_2, SQ3_2, 0.f, -SQ3_2, -SQ3_2};
__host__ __device__ constexpr int md(int x, int m) { return ((x % m) + m) % m; }

__constant__ float C_FACTF[11] = {1.f,1.f,2.f,6.f,24.f,120.f,720.f,5040.f,
                                  40320.f,362880.f,3628800.f};

__device__ float  g_w_l2[6];
__device__ float2 g_e20[20], g_e12[12];
__device__ __align__(16) float  g_DS2 [1320];   // [l6][k20][m'+5]  (quad-weighted)
__device__ __align__(16) float  g_TD1C[5184];   // [l6][k12][mq6][j12 pad] *(2l+1), m'>=0 only
__device__ __align__(16) float  g_DSO3[900];    // [l3][k12][m2+2][p2+2] *w
__device__ __align__(16) float  g_TD2 [450];    // [l3][k6][m2+2][p2+2] *(2l+1)
__device__ __align__(16) float2 g_CY1 [528];    // [l6][o8][p'+5]
__device__ __align__(16) float2 g_CY2 [9600];   // [l3][f8][o16][j2+2][k2+2]
__device__ float  g_feat[2048*16];
__device__ unsigned g_ctr;

__device__ float wig_df(int l, int mp, int m, float beta) {
    if (mp < -l || mp > l || m < -l || m > l) return 0.f;
    float c = cosf(0.5f*beta), s = sinf(0.5f*beta);
    int k0 = max(0, m - mp), k1 = min(l + m, l - mp);
    if (k1 < k0) return 0.f;
    float pre = sqrtf(C_FACTF[l+mp]*C_FACTF[l-mp]*C_FACTF[l+m]*C_FACTF[l-m]);
    float acc = 0.f;
    for (int k = k0; k <= k1; k++) {
        float t = pre/(C_FACTF[l+m-k]*C_FACTF[k]*C_FACTF[mp-m+k]*C_FACTF[l-mp-k]);
        int ec = 2*l - 2*k + m - mp, es = mp - m + 2*k;
        float pc = 1.f, ps = 1.f;
        for (int i = 0; i < ec; i++) pc *= c;
        for (int i = 0; i < es; i++) ps *= s;
        acc += (((mp - m + k) & 1) ? -t : t) * pc * ps;
    }
    return acc;
}

__device__ float quad_w(int k, int b) {   // Driscoll-Healy weight, fp32
    float beta = PI_F*(2*k+1)/(4.0f*b), ss = 0.f;
    for (int j = 0; j < b; j++) ss += sinf((2*j+1)*beta)/(float)(2*j+1);
    return (2.0f/b)*sinf(beta)*ss;
}

// Tables WITHOUT psi (psi moved into k_weights): 1320+5184+900+450+38 = 7892
__global__ void k_tables() {
    const int N0=1320, N1=5184, N2=900, N3=450, N6=38;
    int stride = gridDim.x * blockDim.x;
    for (int e = blockIdx.x*blockDim.x + threadIdx.x; e < N0+N1+N2+N3+N6; e += stride) {
        int i = e;
        if (i < N0) {
            int j = i%11, k = (i/11)%20, l = i/220;
            g_DS2[i] = wig_df(l, j-5, 0, PI_F*(2*k+1)/40.0f) * quad_w(k, 10);
            continue;
        }
        i -= N0;
        if (i < N1) {  // TD1C[l][k][mq][j12]: m' = mq (0..5), m = j-5
            int j = i%12, mq = (i/12)%6, k = (i/72)%12, l = i/864;
            g_TD1C[i] = (j < 11) ? (float)(2*l+1)*wig_df(l, mq, j-5, PI_F*(2*k+1)/24.0f) : 0.f;
            continue;
        }
        i -= N1;
        if (i < N2) {
            int j = i%5, mi = (i/5)%5, k = (i/25)%12, l = i/300;
            g_DSO3[i] = wig_df(l, mi-2, j-2, PI_F*(2*k+1)/24.0f) * quad_w(k, 6);
            continue;
        }
        i -= N2;
        if (i < N3) {
            int j = i%5, mi = (i/5)%5, k = (i/25)%6, l = i/150;
            g_TD2[i] = (float)(2*l+1) * wig_df(l, mi-2, j-2, PI_F*(2*k+1)/12.0f);
            continue;
        }
        i -= N3;
        if (i < 20)      { float a = 2.0f*PI_F*i/20.0f; g_e20[i] = make_float2(cosf(a), sinf(a)); }
        else if (i < 32) { float a = 2.0f*PI_F*(i-20)/12.0f; g_e12[i-20] = make_float2(cosf(a), sinf(a)); }
        else             g_w_l2[i-32] = quad_w(i-32, 3);
    }
}

// Weight spectra with psi computed into smem.
// Blocks 0..11: CY2 (l = b/4, output part = b%4 of 3200). Block 12: CY1.
__global__ void k_weights(const float* __restrict__ w1, const float* __restrict__ w2) {
    __shared__ float2 s_psi[3600];
    int b = blockIdx.x, tid = threadIdx.x;
    if (b < 12) {
        int l = b >> 2, part = b & 3;
        for (int i = tid; i < 3600; i += 512) {
            int j = i % 5, mi = (i/5) % 5, g = i / 25;
            int m = mi - 2, p = j - 2;
            float bb = (float)(g/48 + 1) * (PI_F/24.0f);
            float al = (float)((g/6)%8) * (PI_F/4.0f);
            float ga = (float)(g%6) * (PI_F/3.0f);
            float d  = wig_df(l, m, p, bb);
            float ang = -((float)m*al + (float)p*ga);
            s_psi[i] = make_float2(d*cosf(ang), d*sinf(ang));
        }
        __syncthreads();
        for (int i = part*800 + tid; i < (part+1)*800; i += 512) {
            int jk = i % 25;                 // j2*5+k2
            int o = (i/25) % 16, f = i/400;
            const float* wp = w2 + (f*16 + o)*144;
            float re0 = 0.f, im0 = 0.f, re1 = 0.f, im1 = 0.f;
            #pragma unroll 4
            for (int g = 0; g < 144; g += 2) {
                float wv0 = wp[g];
                float2 p0 = s_psi[g*25 + jk];
                re0 += wv0*p0.x; im0 += wv0*p0.y;
                float wv1 = wp[g+1];
                float2 p1 = s_psi[(g+1)*25 + jk];
                re1 += wv1*p1.x; im1 += wv1*p1.y;
            }
            g_CY2[l*3200 + i] = make_float2(re0 + re1, -(im0 + im1));
        }
    } else {
        // PSI1: [l6][g24][m'+5] = 1584 entries
        for (int i = tid; i < 1584; i += 512) {
            int j = i % 11, g = (i/11) % 24, l = i/264;
            int mp = j - 5;
            float bb = (float)(g/8 + 1) * (PI_F/24.0f);
            float al = (float)(g%8) * (PI_F/4.0f);
            float d  = wig_df(l, mp, 0, bb);
            float ang = -(float)mp * al;
            s_psi[i] = make_float2(d*cosf(ang), d*sinf(ang));
        }
        __syncthreads();
        for (int i = tid; i < 528; i += 512) {   // FIX: loop, not guard (528 > 512)
            int j = i % 11, o = (i/11) % 8, l = i/88;
            float re = 0.f, im = 0.f;
            #pragma unroll
            for (int g = 0; g < 24; g++) {
                float wv = w1[o*24 + g];
                float2 ps = s_psi[(l*24 + g)*11 + j];
                re += wv*ps.x; im += wv*ps.y;
            }
            g_CY1[i] = make_float2(re, -im);
        }
    }
}

__device__ __forceinline__ float2 cfma(float2 a, float2 b, float2 c) {
    c.x += a.x*b.x - a.y*b.y;
    c.y += a.x*b.y + a.y*b.x;
    return c;
}
__device__ __forceinline__ void cfmac(float2 f, float wx, float wy, float2& c) {
    c.x += f.x*wx - f.y*wy;
    c.y += f.x*wy + f.y*wx;
}

#define SM_FLOATS (256 + 2*13824)
#define SM_BYTES  (SM_FLOATS*4)

// Ph4+5 body: jacc = sum_{l>=mq} TD1C*P (smem), radix-2 gamma synthesis -> G
__device__ __forceinline__ void ph45_body(const float* __restrict__ sTD1,
                                          const float2* __restrict__ P,
                                          float2* __restrict__ G,
                                          int mq, int o, int kk) {
    float2 jacc[12];
    #pragma unroll
    for (int j = 0; j < 12; j++) jacc[j] = make_float2(0.f, 0.f);
    for (int l = mq; l < 6; l++) {
        const float4* dp4 = (const float4*)(sTD1 + ((l*12 + kk)*6 + mq)*12);
        const float4* pp4 = (const float4*)(P + ((l*8 + o)*6 + mq)*12);
        #pragma unroll
        for (int q = 0; q < 3; q++) {
            float4 d  = dp4[q];
            float4 pa = pp4[2*q], pb = pp4[2*q+1];
            jacc[4*q+0].x += d.x*pa.x; jacc[4*q+0].y += d.x*pa.y;
            jacc[4*q+1].x += d.y*pa.z; jacc[4*q+1].y += d.y*pa.w;
            jacc[4*q+2].x += d.z*pb.x; jacc[4*q+2].y += d.z*pb.y;
            jacc[4*q+3].x += d.w*pb.z; jacc[4*q+3].y += d.w*pb.w;
        }
    }
    float2* gp = G + ((o*12 + kk)*6 + mq)*12;
    #pragma unroll
    for (int g1 = 0; g1 < 6; g1++) {
        float2 Se = make_float2(0.f, 0.f), So = make_float2(0.f, 0.f);
        #pragma unroll
        for (int j = 1; j < 11; j += 2)   // p' even
            cfmac(jacc[j], CE12X[md((j-5)*g1,12)], CE12Y[md((j-5)*g1,12)], Se);
        #pragma unroll
        for (int j = 0; j < 11; j += 2)   // p' odd
            cfmac(jacc[j], CE12X[md((j-5)*g1,12)], CE12Y[md((j-5)*g1,12)], So);
        gp[g1]     = make_float2(Se.x + So.x, Se.y + So.y);
        gp[g1 + 6] = make_float2(Se.x - So.x, Se.y - So.y);
    }
}

__global__ void __launch_bounds__(512, 2)
k_forward(const float* __restrict__ x, const float* __restrict__ b1,
          const float* __restrict__ b2, const float* __restrict__ w_out,
          const float* __restrict__ b_out, float* __restrict__ out) {
    extern __shared__ float sm[];
    float2* se20 = (float2*)(sm);        // 20c
    float2* se12 = (float2*)(sm + 40);   // 12c
    float*  sb1  = sm + 76;              // 8
    float*  sb2  = sm + 84;              // 16
    float*  swi  = sm + 100;             // 6
    float2* sXS  = (float2*)(sm + 108);  // 66c
    float*  A    = sm + 256;
    float*  Bb   = sm + 256 + 13824;
    __shared__ unsigned s_last;

    const int tid = threadIdx.x;
    const int n = blockIdx.x;

    if (tid < 20)                se20[tid]     = g_e20[tid];
    if (tid >= 32  && tid < 44)  se12[tid-32]  = g_e12[tid-32];
    if (tid >= 96  && tid < 104) sb1 [tid-96]  = b1[tid-96];
    if (tid >= 128 && tid < 144) sb2 [tid-128] = b2[tid-128];
    if (tid >= 160 && tid < 166) swi [tid-160] = g_w_l2[tid-160] * (1.f/36.f);

    // Ph0: load x[n] (20x20) into A[0..400)
    float* sx = A;
    for (int i = tid; i < 400; i += 512) sx[i] = x[n*400 + i];
    __syncthreads();

    // Ph1: alpha analysis Xf[k][m'+5] (B). Idle threads stage TD1C into A[6912..12096).
    float2* Xf = (float2*)Bb;
    float* sTD1 = A + 6912;
    if (tid < 220) {
        int k = tid/11, mp = tid%11 - 5;
        int s = (20 - mp) % 20;
        const float* xp = sx + k*20;
        float re = 0.f, im = 0.f;
        int r = 0;
        #pragma unroll
        for (int a = 0; a < 20; a++) {
            float v = xp[a];
            float2 w = se20[r];
            re += v*w.x; im += v*w.y;
            r += s; if (r >= 20) r -= 20;
        }
        Xf[tid] = make_float2(re, im);
    } else if (tid >= 256) {
        float4* dst = (float4*)sTD1;
        const float4* src = (const float4*)g_TD1C;
        for (int i = tid - 256; i < 1296; i += 256) dst[i] = src[i];
    }
    __syncthreads();

    // Ph2: XS[l][m'+5] = sum_k DS2 * Xf
    if (tid < 66) {
        int l = tid/11, j = tid%11;
        float2 acc = make_float2(0.f, 0.f);
        #pragma unroll
        for (int k = 0; k < 20; k++) {
            float d = g_DS2[(l*20 + k)*11 + j];
            float2 v = Xf[k*11 + j];
            acc.x += d*v.x; acc.y += d*v.y;
        }
        sXS[tid] = acc;
    }
    __syncthreads();

    // Ph3: P[l][o][mq][j12 pad] = XS * CY1   (A[0..6912))
    float2* P = (float2*)A;
    if (tid < 288) {
        int mq = tid % 6, o = (tid/6) % 8, l = tid/48;
        float2 xs = sXS[l*11 + mq + 5];
        const float2* cy = g_CY1 + (l*8 + o)*11;
        float2* op = P + ((l*8 + o)*6 + mq)*12;
        #pragma unroll
        for (int j = 0; j < 11; j++) {
            float2 c = cy[j];
            op[j] = make_float2(xs.x*c.x - xs.y*c.y, xs.x*c.y + xs.y*c.x);
        }
        op[11] = make_float2(0.f, 0.f);
    }
    __syncthreads();

    // Ph4+5 fused, BALANCED: threads 0-479 take one item (mq = tid/96, max 6 l-iters);
    // threads 480-511 take the three cheap mq=5 items (3 x 1 l-iter).
    float2* G = (float2*)Bb;
    if (tid < 480) {
        int mq = tid / 96;
        int r  = tid % 96;
        ph45_body(sTD1, P, G, mq, r/12, r%12);
    } else {
        int base = tid - 480;
        #pragma unroll
        for (int s = 0; s < 3; s++) {
            int r = base + 32*s;
            ph45_body(sTD1, P, G, 5, r/12, r%12);
        }
    }
    __syncthreads();

    // Ph6: alpha synthesis (Hermitian, radix-2) + bias + ReLU -> h1[f][k][a][g] (A)
    float* h1 = A;
    for (int t = tid; t < 1152; t += 512) {
        int g = t % 12, kk = (t/12) % 12, f = t/144;
        const float2* Gp = G + (f*12 + kk)*72 + g;
        float2 gm1 = Gp[12], gm2 = Gp[24], gm3 = Gp[36], gm4 = Gp[48], gm5 = Gp[60];
        float g0 = Gp[0].x;
        float bb = sb1[f];
        float* op = h1 + ((f*12 + kk)*12)*12 + g;
        #pragma unroll
        for (int a1 = 0; a1 < 6; a1++) {
            float E = g0
                + 2.f*(gm2.x*CE12X[md(2*a1,12)] - gm2.y*CE12Y[md(2*a1,12)])
                + 2.f*(gm4.x*CE12X[md(4*a1,12)] - gm4.y*CE12Y[md(4*a1,12)]);
            float O =
                  2.f*(gm1.x*CE12X[md(a1,12)]   - gm1.y*CE12Y[md(a1,12)])
                + 2.f*(gm3.x*CE12X[md(3*a1,12)] - gm3.y*CE12Y[md(3*a1,12)])
                + 2.f*(gm5.x*CE12X[md(5*a1,12)] - gm5.y*CE12Y[md(5*a1,12)]);
            op[a1*12]       = fmaxf(E + O + bb, 0.f);
            op[(a1 + 6)*12] = fmaxf(E - O + bb, 0.f);
        }
    }
    __syncthreads();

    // Ph7: gamma analysis T[f][k][a][p2] (B). Radix-2 in g.
    float2* T = (float2*)Bb;
    for (int t = tid; t < 1152; t += 512) {
        int a = t % 12, kk = (t/12) % 12, f = t/144;
        const float4* hp4 = (const float4*)(h1 + ((f*12 + kk)*12 + a)*12);
        float h[12];
        #pragma unroll
        for (int q = 0; q < 3; q++) {
            float4 v = hp4[q];
            h[4*q] = v.x; h[4*q+1] = v.y; h[4*q+2] = v.z; h[4*q+3] = v.w;
        }
        float he[6], ho[6];
        #pragma unroll
        for (int g1 = 0; g1 < 6; g1++) { he[g1] = h[g1] + h[g1+6]; ho[g1] = h[g1] - h[g1+6]; }
        float2* op = T + ((f*12 + kk)*12 + a)*3;
        op[0] = make_float2(he[0]+he[1]+he[2]+he[3]+he[4]+he[5], 0.f);
        {
            float re = 0.f, im = 0.f;
            #pragma unroll
            for (int g1 = 0; g1 < 6; g1++) {
                re += ho[g1]*CE12X[g1];
                im -= ho[g1]*CE12Y[g1];
            }
            op[1] = make_float2(re, im);
        }
        {
            float re = 0.f, im = 0.f;
            #pragma unroll
            for (int g1 = 0; g1 < 6; g1++) {
                re += he[g1]*CE12X[md(2*g1,12)];
                im -= he[g1]*CE12Y[md(2*g1,12)];
            }
            op[2] = make_float2(re, im);
        }
    }
    __syncthreads();

    // Ph8: alpha analysis F2h[f][k][m2][p2+2] (A), only m2 = 0..2 (i2 = 2..4)
    float2* F2h = (float2*)A;
    if (tid < 288) {
        int m2 = tid % 3, kk = (tid/3) % 12, f = tid/36;
        int i2 = m2 + 2;
        int s = (12 - m2) % 12;
        float2 acc[5];
        #pragma unroll
        for (int j = 0; j < 5; j++) acc[j] = make_float2(0.f, 0.f);
        const float2* Tp = T + ((f*12 + kk)*12)*3;
        int r = 0;
        #pragma unroll
        for (int a = 0; a < 12; a++) {
            float2 t0 = Tp[a*3+0], t1 = Tp[a*3+1], t2 = Tp[a*3+2];
            float2 tw = se12[r];
            acc[0] = cfma(make_float2(t2.x, -t2.y), tw, acc[0]);
            acc[1] = cfma(make_float2(t1.x, -t1.y), tw, acc[1]);
            acc[2] = cfma(t0, tw, acc[2]);
            acc[3] = cfma(t1, tw, acc[3]);
            acc[4] = cfma(t2, tw, acc[4]);
            r += s; if (r >= 12) r -= 12;
        }
        float2* op = F2h + ((f*12 + kk)*5 + i2)*5;
        #pragma unroll
        for (int j = 0; j < 5; j++) op[j] = acc[j];
    }
    __syncthreads();

    // Ph9: XS2[l][f][i2][k2] = sum_k F2h * DSO3   (B), only i2 = 2..4
    float2* XS2 = (float2*)Bb;
    if (tid < 72) {
        int i2 = tid % 3 + 2, f = (tid/3) % 8, l = tid/24;
        float2 acc[5];
        #pragma unroll
        for (int j = 0; j < 5; j++) acc[j] = make_float2(0.f, 0.f);
        #pragma unroll
        for (int k = 0; k < 12; k++) {
            const float* dp = g_DSO3 + ((l*12 + k)*5 + i2)*5;
            const float2* vp = F2h + ((f*12 + k)*5 + i2)*5;
            #pragma unroll
            for (int j = 0; j < 5; j++) {
                float d = dp[j];
                acc[j].x += d*vp[j].x; acc[j].y += d*vp[j].y;
            }
        }
        float2* op = XS2 + ((l*8 + f)*5 + i2)*5;
        #pragma unroll
        for (int j = 0; j < 5; j++) op[j] = acc[j];
    }
    __syncthreads();

    // Ph10: warp-cooperative Z2[l][o][i2][j2] (A), only i2 = 2..4.
    float2* Z2 = (float2*)A;
    {
        int w = tid >> 5, lane = tid & 31;
        int j2 = lane / 5, k2 = lane % 5;
        int cl = (lane < 25) ? lane : 24;
        #pragma unroll
        for (int it = 0; it < 3; it++) {
            int idx = it*16 + w;          // 0..47
            int l = idx >> 4, o = idx & 15;
            float2 acc[3];
            #pragma unroll
            for (int q = 0; q < 3; q++) acc[q] = make_float2(0.f, 0.f);
            #pragma unroll
            for (int f = 0; f < 8; f++) {
                float2 cy = g_CY2[((l*8 + f)*16 + o)*25 + cl];
                const float2* xb = XS2 + (l*8 + f)*25 + k2;
                #pragma unroll
                for (int q = 0; q < 3; q++)
                    acc[q] = cfma(xb[(q+2)*5], cy, acc[q]);
            }
            #pragma unroll
            for (int q = 0; q < 3; q++) {
                float rx = acc[q].x, ry = acc[q].y;
                #pragma unroll
                for (int d = 1; d < 5; d++) {
                    rx += __shfl_down_sync(0xffffffffu, acc[q].x, d);
                    ry += __shfl_down_sync(0xffffffffu, acc[q].y, d);
                }
                if (k2 == 0 && j2 < 5)
                    Z2[((l*16 + o)*5 + (q+2))*5 + j2] = make_float2(rx, ry);
            }
        }
    }
    __syncthreads();

    // Ph11 fused: jacc = sum_{l>=mq} TD2*Z2 (regs), radix-2 gamma synthesis -> G2 (B)
    float2* G2 = (float2*)Bb;
    if (tid < 288) {
        int mq = tid / 96;
        int r  = tid % 96;
        int o  = r / 6, kk = r % 6;
        float2 jacc[5];
        #pragma unroll
        for (int j = 0; j < 5; j++) jacc[j] = make_float2(0.f, 0.f);
        for (int l = mq; l < 3; l++) {
            const float* dp = g_TD2 + ((l*6 + kk)*5 + (mq+2))*5;
            const float2* zp = Z2 + ((l*16 + o)*5 + (mq+2))*5;
            #pragma unroll
            for (int j = 0; j < 5; j++) {
                float d = dp[j];
                jacc[j].x += d*zp[j].x; jacc[j].y += d*zp[j].y;
            }
        }
        float2* gp = G2 + ((o*6 + kk)*3 + mq)*6;
        #pragma unroll
        for (int g1 = 0; g1 < 3; g1++) {
            float2 Se = make_float2(0.f, 0.f), So = make_float2(0.f, 0.f);
            cfmac(jacc[0], CE6X[md(-2*g1,6)], CE6Y[md(-2*g1,6)], Se);
            Se.x += jacc[2].x; Se.y += jacc[2].y;
            cfmac(jacc[4], CE6X[md(2*g1,6)], CE6Y[md(2*g1,6)], Se);
            cfmac(jacc[1], CE6X[md(-g1,6)], CE6Y[md(-g1,6)], So);
            cfmac(jacc[3], CE6X[md(g1,6)],  CE6Y[md(g1,6)],  So);
            gp[g1]     = make_float2(Se.x + So.x, Se.y + So.y);
            gp[g1 + 3] = make_float2(Se.x - So.x, Se.y - So.y);
        }
    }
    __syncthreads();

    // Ph12: alpha synthesis (Hermitian) + bias + ReLU, pre-weighted -> h2 (A)
    float* h2 = A;
    for (int t = tid; t < 576; t += 512) {
        int g = t % 6, kk = (t/6) % 6, o = t/36;
        const float2* Gp = G2 + (o*6 + kk)*18 + g;
        float2 g0 = Gp[0], g1 = Gp[6], g2 = Gp[12];
        float g1x = 2.f*g1.x, g1y = 2.f*g1.y, g2x = 2.f*g2.x, g2y = 2.f*g2.y;
        float bb = sb2[o];
        float wk = swi[kk];
        float* op = h2 + ((o*6 + kk)*6)*6 + g;
        #pragma unroll
        for (int a = 0; a < 6; a++) {
            float v = g0.x + g1x*CE6X[md(a,6)] - g1y*CE6Y[md(a,6)]
                           + g2x*CE6X[md(2*a,6)] - g2y*CE6Y[md(2*a,6)];
            op[a*6] = fmaxf(v + bb, 0.f) * wk;
        }
    }
    __syncthreads();

    // Ph13: integrate: feat[n][o] = sum over pre-weighted h2
    {
        int w = tid >> 5, lane = tid & 31;
        const float* hp = h2 + w*216;
        float s = 0.f;
        #pragma unroll
        for (int idx = lane; idx < 216; idx += 32)
            s += hp[idx];
        #pragma unroll
        for (int off = 16; off; off >>= 1)
            s += __shfl_down_sync(0xffffffffu, s, off);
        if (lane == 0) g_feat[n*16 + w] = s;
    }

    // Fused final: last CTA does maxpool + linear
    __threadfence();
    __syncthreads();
    if (tid == 0) {
        unsigned old = atomicAdd(&g_ctr, 1u);
        s_last = (old == (unsigned)(gridDim.x - 1)) ? 1u : 0u;
    }
    __syncthreads();
    if (s_last) {
        __threadfence();
        float* sp = A;
        float* pooled = A + 512;
        for (int b = 0; b < 4; b++) {
            int o = tid & 15, grp = tid >> 4;
            float m = -3.4e38f;
            #pragma unroll
            for (int j = 0; j < 16; j++) {
                int p = grp + j*32;
                m = fmaxf(m, g_feat[(b*512 + p)*16 + o]);
            }
            sp[grp*16 + o] = m;
            __syncthreads();
            if (tid < 16) {
                float mm = sp[tid];
                for (int g2 = 1; g2 < 32; g2++) mm = fmaxf(mm, sp[g2*16 + tid]);
                pooled[tid] = mm;
            }
            __syncthreads();
            if (tid < 10) {
                float acc = b_out[tid];
                #pragma unroll
                for (int o2 = 0; o2 < 16; o2++) acc += pooled[o2]*w_out[tid*16 + o2];
                out[b*10 + tid] = acc;
            }
            __syncthreads();
        }
        if (tid == 0) g_ctr = 0;
    }
}

extern "C" void kernel_launch(void* const* d_in, const int* in_sizes, int n_in,
                              void* d_out, int out_size) {
    const float* x     = (const float*)d_in[0];
    const float* w1    = (const float*)d_in[1];
    const float* b1    = (const float*)d_in[2];
    const float* w2    = (const float*)d_in[3];
    const float* b2    = (const float*)d_in[4];
    const float* w_out = (const float*)d_in[5];
    const float* b_out = (const float*)d_in[6];
    float* out = (float*)d_out;

    cudaFuncSetAttribute(k_forward, cudaFuncAttributeMaxDynamicSharedMemorySize, SM_BYTES);

    k_tables<<<16, 512>>>();
    k_weights<<<13, 512>>>(w1, w2);
    k_forward<<<2048, 512, SM_BYTES>>>(x, b1, b2, w_out, b_out, out);
}

// round 16
// speedup vs baseline: 1.4408x; 1.0671x over previous
#include <cuda_runtime.h>

#define PI_F 3.14159265358979323846f

// exact compile-time twiddles (roots of unity for N=12 and N=6)
#define SQ3_2 0.86602540378443864676f
static __device__ constexpr float CE12X[12] = {1.f, SQ3_2, .5f, 0.f, -.5f, -SQ3_2, -1.f, -SQ3_2, -.5f, 0.f, .5f, SQ3_2};
static __device__ constexpr float CE12Y[12] = {0.f, .5f, SQ3_2, 1.f, SQ3_2, .5f, 0.f, -.5f, -SQ3_2, -1.f, -SQ3_2, -.5f};
static __device__ constexpr float CE6X[6]   = {1.f, .5f, -.5f, -1.f, -.5f, .5f};
static __device__ constexpr float CE6Y[6]   = {0.f, SQ3_2, SQ3_2, 0.f, -SQ3_2, -SQ3_2};
__host__ __device__ constexpr int md(int x, int m) { return ((x % m) + m) % m; }

__constant__ float C_FACTF[11] = {1.f,1.f,2.f,6.f,24.f,120.f,720.f,5040.f,
                                  40320.f,362880.f,3628800.f};

__device__ float  g_w_l2[6];
__device__ float2 g_e20[20], g_e12[12];
__device__ __align__(16) float  g_DS2 [1320];   // [l6][k20][m'+5]  (quad-weighted)
__device__ __align__(16) float  g_TD1C[5184];   // [l6][k12][mq6][j12 pad] *(2l+1), m'>=0 only
__device__ __align__(16) float  g_DSO3[900];    // [l3][k12][m2+2][p2+2] *w
__device__ __align__(16) float  g_TD2 [450];    // [l3][k6][m2+2][p2+2] *(2l+1)
__device__ __align__(16) float2 g_PSI1[1584];   // [l6][g24][m'+5]
__device__ __align__(16) float2 g_PSI2[10800];  // [l3][g144][m+2][p+2]
__device__ __align__(16) float2 g_CY1 [528];    // [l6][o8][p'+5]
__device__ __align__(16) float2 g_CY2 [9600];   // [l3][f8][o16][j2+2][k2+2]
__device__ float  g_feat[2048*16];
__device__ unsigned g_ctr;

__device__ float wig_df(int l, int mp, int m, float beta) {
    if (mp < -l || mp > l || m < -l || m > l) return 0.f;
    float c = cosf(0.5f*beta), s = sinf(0.5f*beta);
    int k0 = max(0, m - mp), k1 = min(l + m, l - mp);
    if (k1 < k0) return 0.f;
    float pre = sqrtf(C_FACTF[l+mp]*C_FACTF[l-mp]*C_FACTF[l+m]*C_FACTF[l-m]);
    float acc = 0.f;
    for (int k = k0; k <= k1; k++) {
        float t = pre/(C_FACTF[l+m-k]*C_FACTF[k]*C_FACTF[mp-m+k]*C_FACTF[l-mp-k]);
        int ec = 2*l - 2*k + m - mp, es = mp - m + 2*k;
        float pc = 1.f, ps = 1.f;
        for (int i = 0; i < ec; i++) pc *= c;
        for (int i = 0; i < es; i++) ps *= s;
        acc += (((mp - m + k) & 1) ? -t : t) * pc * ps;
    }
    return acc;
}

__device__ float quad_w(int k, int b) {   // Driscoll-Healy weight, fp32
    float beta = PI_F*(2*k+1)/(4.0f*b), ss = 0.f;
    for (int j = 0; j < b; j++) ss += sinf((2*j+1)*beta)/(float)(2*j+1);
    return (2.0f/b)*sinf(beta)*ss;
}

__global__ void k_tables() {
    const int N0=1320, N1=5184, N2=900, N3=450, N4=1584, N5=10800, N6=38;
    int stride = gridDim.x * blockDim.x;
    for (int e = blockIdx.x*blockDim.x + threadIdx.x; e < N0+N1+N2+N3+N4+N5+N6; e += stride) {
        int i = e;
        if (i < N0) {
            int j = i%11, k = (i/11)%20, l = i/220;
            g_DS2[i] = wig_df(l, j-5, 0, PI_F*(2*k+1)/40.0f) * quad_w(k, 10);
            continue;
        }
        i -= N0;
        if (i < N1) {  // TD1C[l][k][mq][j12]: m' = mq (0..5), m = j-5
            int j = i%12, mq = (i/12)%6, k = (i/72)%12, l = i/864;
            g_TD1C[i] = (j < 11) ? (float)(2*l+1)*wig_df(l, mq, j-5, PI_F*(2*k+1)/24.0f) : 0.f;
            continue;
        }
        i -= N1;
        if (i < N2) {
            int j = i%5, mi = (i/5)%5, k = (i/25)%12, l = i/300;
            g_DSO3[i] = wig_df(l, mi-2, j-2, PI_F*(2*k+1)/24.0f) * quad_w(k, 6);
            continue;
        }
        i -= N2;
        if (i < N3) {
            int j = i%5, mi = (i/5)%5, k = (i/25)%6, l = i/150;
            g_TD2[i] = (float)(2*l+1) * wig_df(l, mi-2, j-2, PI_F*(2*k+1)/12.0f);
            continue;
        }
        i -= N3;
        if (i < N4) {
            int j = i%11, g = (i/11)%24, l = i/264;
            int mp = j - 5;
            float b  = (float)(g/8 + 1) * (PI_F/24.0f);
            float al = (float)(g%8) * (PI_F/4.0f);
            float d  = wig_df(l, mp, 0, b);
            float ang = -(float)mp * al;
            g_PSI1[i] = make_float2(d*cosf(ang), d*sinf(ang));
            continue;
        }
        i -= N4;
        if (i < N5) {
            int j = i%5, mi = (i/5)%5, g = (i/25)%144, l = i/3600;
            int m = mi - 2, p = j - 2;
            float b  = (float)(g/48 + 1) * (PI_F/24.0f);
            float al = (float)((g/6)%8) * (PI_F/4.0f);
            float ga = (float)(g%6) * (PI_F/3.0f);
            float d  = wig_df(l, m, p, b);
            float ang = -((float)m*al + (float)p*ga);
            g_PSI2[i] = make_float2(d*cosf(ang), d*sinf(ang));
            continue;
        }
        i -= N5;
        if (i < 20)      { float a = 2.0f*PI_F*i/20.0f; g_e20[i] = make_float2(cosf(a), sinf(a)); }
        else if (i < 32) { float a = 2.0f*PI_F*(i-20)/12.0f; g_e12[i-20] = make_float2(cosf(a), sinf(a)); }
        else             g_w_l2[i-32] = quad_w(i-32, 3);
    }
}

__global__ void k_weights(const float* __restrict__ w1, const float* __restrict__ w2) {
    const int NC1 = 528, NC2 = 9600;
    int stride = gridDim.x * blockDim.x;
    for (int e = blockIdx.x*blockDim.x + threadIdx.x; e < NC1+NC2; e += stride) {
        if (e < NC1) {
            int j = e%11, o = (e/11)%8, l = e/88;
            float re = 0.f, im = 0.f;
            for (int g = 0; g < 24; g++) {
                float wv = w1[o*24 + g];
                float2 ps = g_PSI1[(l*24 + g)*11 + j];
                re += wv*ps.x; im += wv*ps.y;
            }
            g_CY1[e] = make_float2(re, -im);
        } else {
            int i = e - NC1;
            int k2 = i%5, j2 = (i/5)%5, o = (i/25)%16, f = (i/400)%8, l = i/3200;
            float re = 0.f, im = 0.f;
            for (int g = 0; g < 144; g++) {
                float wv = w2[(f*16 + o)*144 + g];
                float2 ps = g_PSI2[((l*144 + g)*5 + j2)*5 + k2];
                re += wv*ps.x; im += wv*ps.y;
            }
            g_CY2[i] = make_float2(re, -im);
        }
    }
}

__device__ __forceinline__ float2 cfma(float2 a, float2 b, float2 c) {
    c.x += a.x*b.x - a.y*b.y;
    c.y += a.x*b.y + a.y*b.x;
    return c;
}
__device__ __forceinline__ void cfmac(float2 f, float wx, float wy, float2& c) {
    c.x += f.x*wx - f.y*wy;
    c.y += f.x*wy + f.y*wx;
}

#define SM_FLOATS (256 + 2*13824)
#define SM_BYTES  (SM_FLOATS*4)

// Ph4+5 body: jacc = sum_{l>=mq} TD1C*P (smem), radix-2 gamma synthesis -> G
__device__ __forceinline__ void ph45_body(const float* __restrict__ sTD1,
                                          const float2* __restrict__ P,
                                          float2* __restrict__ G,
                                          int mq, int o, int kk) {
    float2 jacc[12];
    #pragma unroll
    for (int j = 0; j < 12; j++) jacc[j] = make_float2(0.f, 0.f);
    for (int l = mq; l < 6; l++) {
        const float4* dp4 = (const float4*)(sTD1 + ((l*12 + kk)*6 + mq)*12);
        const float4* pp4 = (const float4*)(P + ((l*8 + o)*6 + mq)*12);
        #pragma unroll
        for (int q = 0; q < 3; q++) {
            float4 d  = dp4[q];
            float4 pa = pp4[2*q], pb = pp4[2*q+1];
            jacc[4*q+0].x += d.x*pa.x; jacc[4*q+0].y += d.x*pa.y;
            jacc[4*q+1].x += d.y*pa.z; jacc[4*q+1].y += d.y*pa.w;
            jacc[4*q+2].x += d.z*pb.x; jacc[4*q+2].y += d.z*pb.y;
            jacc[4*q+3].x += d.w*pb.z; jacc[4*q+3].y += d.w*pb.w;
        }
    }
    float2* gp = G + ((o*12 + kk)*6 + mq)*12;
    #pragma unroll
    for (int g1 = 0; g1 < 6; g1++) {
        float2 Se = make_float2(0.f, 0.f), So = make_float2(0.f, 0.f);
        #pragma unroll
        for (int j = 1; j < 11; j += 2)   // p' even
            cfmac(jacc[j], CE12X[md((j-5)*g1,12)], CE12Y[md((j-5)*g1,12)], Se);
        #pragma unroll
        for (int j = 0; j < 11; j += 2)   // p' odd
            cfmac(jacc[j], CE12X[md((j-5)*g1,12)], CE12Y[md((j-5)*g1,12)], So);
        gp[g1]     = make_float2(Se.x + So.x, Se.y + So.y);
        gp[g1 + 6] = make_float2(Se.x - So.x, Se.y - So.y);
    }
}

__global__ void __launch_bounds__(512, 2)
k_forward(const float* __restrict__ x, const float* __restrict__ b1,
          const float* __restrict__ b2, const float* __restrict__ w_out,
          const float* __restrict__ b_out, float* __restrict__ out) {
    extern __shared__ float sm[];
    float2* se20 = (float2*)(sm);        // 20c
    float2* se12 = (float2*)(sm + 40);   // 12c
    float*  sb1  = sm + 76;              // 8
    float*  sb2  = sm + 84;              // 16
    float*  swi  = sm + 100;             // 6
    float*  A    = sm + 256;
    float*  Bb   = sm + 256 + 13824;
    __shared__ unsigned s_last;

    const int tid = threadIdx.x;
    const int n = blockIdx.x;

    if (tid < 20)                se20[tid]     = g_e20[tid];
    if (tid >= 32  && tid < 44)  se12[tid-32]  = g_e12[tid-32];
    if (tid >= 96  && tid < 104) sb1 [tid-96]  = b1[tid-96];
    if (tid >= 128 && tid < 144) sb2 [tid-128] = b2[tid-128];
    if (tid >= 160 && tid < 166) swi [tid-160] = g_w_l2[tid-160] * (1.f/36.f);

    // Ph0: load x[n] (20x20) into A[0..400)
    float* sx = A;
    for (int i = tid; i < 400; i += 512) sx[i] = x[n*400 + i];
    __syncthreads();

    // Ph1: alpha analysis Xf[k][m'+5] (B). Idle threads stage TD1C into A[6912..12096).
    float2* Xf = (float2*)Bb;
    float* sTD1 = A + 6912;
    if (tid < 220) {
        int k = tid/11, mp = tid%11 - 5;
        int s = (20 - mp) % 20;
        const float* xp = sx + k*20;
        float re = 0.f, im = 0.f;
        int r = 0;
        #pragma unroll
        for (int a = 0; a < 20; a++) {
            float v = xp[a];
            float2 w = se20[r];
            re += v*w.x; im += v*w.y;
            r += s; if (r >= 20) r -= 20;
        }
        Xf[tid] = make_float2(re, im);
    } else if (tid >= 256) {
        float4* dst = (float4*)sTD1;
        const float4* src = (const float4*)g_TD1C;
        for (int i = tid - 256; i < 1296; i += 256) dst[i] = src[i];
    }
    __syncthreads();

    // Ph2+3 merged: each (l,o,mq) thread computes its own XS value (20-iter dot,
    // only j=mq+5 is ever needed) then applies CY1 -> P. Removes one barrier.
    float2* P = (float2*)A;
    if (tid < 288) {
        int mq = tid % 6, o = (tid/6) % 8, l = tid/48;
        int j = mq + 5;
        float2 xs = make_float2(0.f, 0.f);
        #pragma unroll
        for (int k = 0; k < 20; k++) {
            float d = g_DS2[(l*20 + k)*11 + j];
            float2 v = Xf[k*11 + j];
            xs.x += d*v.x; xs.y += d*v.y;
        }
        const float2* cy = g_CY1 + (l*8 + o)*11;
        float2* op = P + ((l*8 + o)*6 + mq)*12;
        #pragma unroll
        for (int jj = 0; jj < 11; jj++) {
            float2 c = cy[jj];
            op[jj] = make_float2(xs.x*c.x - xs.y*c.y, xs.x*c.y + xs.y*c.x);
        }
        op[11] = make_float2(0.f, 0.f);
    }
    __syncthreads();

    // Ph4+5 fused, BALANCED: threads 0-479 one item each (mq = tid/96);
    // threads 384-479 (first item mq=4, cheap) also take one mq=5 item each.
    float2* G = (float2*)Bb;
    if (tid < 480) {
        int mq = tid / 96;
        int r  = tid % 96;
        ph45_body(sTD1, P, G, mq, r/12, r%12);
        if (tid >= 384) {
            int r2 = tid - 384;        // items 480..575, all mq=5
            ph45_body(sTD1, P, G, 5, r2/12, r2%12);
        }
    }
    __syncthreads();

    // Ph6: alpha synthesis (Hermitian, radix-2) + bias + ReLU -> h1[f][k][a][g] (A)
    float* h1 = A;
    for (int t = tid; t < 1152; t += 512) {
        int g = t % 12, kk = (t/12) % 12, f = t/144;
        const float2* Gp = G + (f*12 + kk)*72 + g;
        float2 gm1 = Gp[12], gm2 = Gp[24], gm3 = Gp[36], gm4 = Gp[48], gm5 = Gp[60];
        float g0 = Gp[0].x;
        float bb = sb1[f];
        float* op = h1 + ((f*12 + kk)*12)*12 + g;
        #pragma unroll
        for (int a1 = 0; a1 < 6; a1++) {
            float E = g0
                + 2.f*(gm2.x*CE12X[md(2*a1,12)] - gm2.y*CE12Y[md(2*a1,12)])
                + 2.f*(gm4.x*CE12X[md(4*a1,12)] - gm4.y*CE12Y[md(4*a1,12)]);
            float O =
                  2.f*(gm1.x*CE12X[md(a1,12)]   - gm1.y*CE12Y[md(a1,12)])
                + 2.f*(gm3.x*CE12X[md(3*a1,12)] - gm3.y*CE12Y[md(3*a1,12)])
                + 2.f*(gm5.x*CE12X[md(5*a1,12)] - gm5.y*CE12Y[md(5*a1,12)]);
            op[a1*12]       = fmaxf(E + O + bb, 0.f);
            op[(a1 + 6)*12] = fmaxf(E - O + bb, 0.f);
        }
    }
    __syncthreads();

    // Ph7: gamma analysis T[f][k][a][p2] (B). Radix-2 in g.
    float2* T = (float2*)Bb;
    for (int t = tid; t < 1152; t += 512) {
        int a = t % 12, kk = (t/12) % 12, f = t/144;
        const float4* hp4 = (const float4*)(h1 + ((f*12 + kk)*12 + a)*12);
        float h[12];
        #pragma unroll
        for (int q = 0; q < 3; q++) {
            float4 v = hp4[q];
            h[4*q] = v.x; h[4*q+1] = v.y; h[4*q+2] = v.z; h[4*q+3] = v.w;
        }
        float he[6], ho[6];
        #pragma unroll
        for (int g1 = 0; g1 < 6; g1++) { he[g1] = h[g1] + h[g1+6]; ho[g1] = h[g1] - h[g1+6]; }
        float2* op = T + ((f*12 + kk)*12 + a)*3;
        op[0] = make_float2(he[0]+he[1]+he[2]+he[3]+he[4]+he[5], 0.f);
        {
            float re = 0.f, im = 0.f;
            #pragma unroll
            for (int g1 = 0; g1 < 6; g1++) {
                re += ho[g1]*CE12X[g1];
                im -= ho[g1]*CE12Y[g1];
            }
            op[1] = make_float2(re, im);
        }
        {
            float re = 0.f, im = 0.f;
            #pragma unroll
            for (int g1 = 0; g1 < 6; g1++) {
                re += he[g1]*CE12X[md(2*g1,12)];
                im -= he[g1]*CE12Y[md(2*g1,12)];
            }
            op[2] = make_float2(re, im);
        }
    }
    __syncthreads();

    // Ph8: alpha analysis F2h[f][k][m2][p2+2] (A), only m2 = 0..2 (i2 = 2..4)
    float2* F2h = (float2*)A;
    if (tid < 288) {
        int m2 = tid % 3, kk = (tid/3) % 12, f = tid/36;
        int i2 = m2 + 2;
        int s = (12 - m2) % 12;
        float2 acc[5];
        #pragma unroll
        for (int j = 0; j < 5; j++) acc[j] = make_float2(0.f, 0.f);
        const float2* Tp = T + ((f*12 + kk)*12)*3;
        int r = 0;
        #pragma unroll
        for (int a = 0; a < 12; a++) {
            float2 t0 = Tp[a*3+0], t1 = Tp[a*3+1], t2 = Tp[a*3+2];
            float2 tw = se12[r];
            acc[0] = cfma(make_float2(t2.x, -t2.y), tw, acc[0]);
            acc[1] = cfma(make_float2(t1.x, -t1.y), tw, acc[1]);
            acc[2] = cfma(t0, tw, acc[2]);
            acc[3] = cfma(t1, tw, acc[3]);
            acc[4] = cfma(t2, tw, acc[4]);
            r += s; if (r >= 12) r -= 12;
        }
        float2* op = F2h + ((f*12 + kk)*5 + i2)*5;
        #pragma unroll
        for (int j = 0; j < 5; j++) op[j] = acc[j];
    }
    __syncthreads();

    // Ph9: XS2[l][f][i2][k2] = sum_k F2h * DSO3   (B), only i2 = 2..4
    float2* XS2 = (float2*)Bb;
    if (tid < 72) {
        int i2 = tid % 3 + 2, f = (tid/3) % 8, l = tid/24;
        float2 acc[5];
        #pragma unroll
        for (int j = 0; j < 5; j++) acc[j] = make_float2(0.f, 0.f);
        #pragma unroll
        for (int k = 0; k < 12; k++) {
            const float* dp = g_DSO3 + ((l*12 + k)*5 + i2)*5;
            const float2* vp = F2h + ((f*12 + k)*5 + i2)*5;
            #pragma unroll
            for (int j = 0; j < 5; j++) {
                float d = dp[j];
                acc[j].x += d*vp[j].x; acc[j].y += d*vp[j].y;
            }
        }
        float2* op = XS2 + ((l*8 + f)*5 + i2)*5;
        #pragma unroll
        for (int j = 0; j < 5; j++) op[j] = acc[j];
    }
    __syncthreads();

    // Ph10: warp-cooperative Z2[l][o][i2][j2] (A), only i2 = 2..4.
    float2* Z2 = (float2*)A;
    {
        int w = tid >> 5, lane = tid & 31;
        int j2 = lane / 5, k2 = lane % 5;
        int cl = (lane < 25) ? lane : 24;
        #pragma unroll
        for (int it = 0; it < 3; it++) {
            int idx = it*16 + w;          // 0..47
            int l = idx >> 4, o = idx & 15;
            float2 acc[3];
            #pragma unroll
            for (int q = 0; q < 3; q++) acc[q] = make_float2(0.f, 0.f);
            #pragma unroll
            for (int f = 0; f < 8; f++) {
                float2 cy = g_CY2[((l*8 + f)*16 + o)*25 + cl];
                const float2* xb = XS2 + (l*8 + f)*25 + k2;
                #pragma unroll
                for (int q = 0; q < 3; q++)
                    acc[q] = cfma(xb[(q+2)*5], cy, acc[q]);
            }
            #pragma unroll
            for (int q = 0; q < 3; q++) {
                float rx = acc[q].x, ry = acc[q].y;
                #pragma unroll
                for (int d = 1; d < 5; d++) {
                    rx += __shfl_down_sync(0xffffffffu, acc[q].x, d);
                    ry += __shfl_down_sync(0xffffffffu, acc[q].y, d);
                }
                if (k2 == 0 && j2 < 5)
                    Z2[((l*16 + o)*5 + (q+2))*5 + j2] = make_float2(rx, ry);
            }
        }
    }
    __syncthreads();

    // Ph11 fused: jacc = sum_{l>=mq} TD2*Z2 (regs), radix-2 gamma synthesis -> G2 (B)
    float2* G2 = (float2*)Bb;
    if (tid < 288) {
        int mq = tid / 96;
        int r  = tid % 96;
        int o  = r / 6, kk = r % 6;
        float2 jacc[5];
        #pragma unroll
        for (int j = 0; j < 5; j++) jacc[j] = make_float2(0.f, 0.f);
        for (int l = mq; l < 3; l++) {
            const float* dp = g_TD2 + ((l*6 + kk)*5 + (mq+2))*5;
            const float2* zp = Z2 + ((l*16 + o)*5 + (mq+2))*5;
            #pragma unroll
            for (int j = 0; j < 5; j++) {
                float d = dp[j];
                jacc[j].x += d*zp[j].x; jacc[j].y += d*zp[j].y;
            }
        }
        float2* gp = G2 + ((o*6 + kk)*3 + mq)*6;
        #pragma unroll
        for (int g1 = 0; g1 < 3; g1++) {
            float2 Se = make_float2(0.f, 0.f), So = make_float2(0.f, 0.f);
            cfmac(jacc[0], CE6X[md(-2*g1,6)], CE6Y[md(-2*g1,6)], Se);
            Se.x += jacc[2].x; Se.y += jacc[2].y;
            cfmac(jacc[4], CE6X[md(2*g1,6)], CE6Y[md(2*g1,6)], Se);
            cfmac(jacc[1], CE6X[md(-g1,6)], CE6Y[md(-g1,6)], So);
            cfmac(jacc[3], CE6X[md(g1,6)],  CE6Y[md(g1,6)],  So);
            gp[g1]     = make_float2(Se.x + So.x, Se.y + So.y);
            gp[g1 + 3] = make_float2(Se.x - So.x, Se.y - So.y);
        }
    }
    __syncthreads();

    // Ph12: alpha synthesis (Hermitian) + bias + ReLU, pre-weighted -> h2 (A)
    float* h2 = A;
    for (int t = tid; t < 576; t += 512) {
        int g = t % 6, kk = (t/6) % 6, o = t/36;
        const float2* Gp = G2 + (o*6 + kk)*18 + g;
        float2 g0 = Gp[0], g1 = Gp[6], g2 = Gp[12];
        float g1x = 2.f*g1.x, g1y = 2.f*g1.y, g2x = 2.f*g2.x, g2y = 2.f*g2.y;
        float bb = sb2[o];
        float wk = swi[kk];
        float* op = h2 + ((o*6 + kk)*6)*6 + g;
        #pragma unroll
        for (int a = 0; a < 6; a++) {
            float v = g0.x + g1x*CE6X[md(a,6)] - g1y*CE6Y[md(a,6)]
                           + g2x*CE6X[md(2*a,6)] - g2y*CE6Y[md(2*a,6)];
            op[a*6] = fmaxf(v + bb, 0.f) * wk;
        }
    }
    __syncthreads();

    // Ph13: integrate: feat[n][o] = sum over pre-weighted h2
    {
        int w = tid >> 5, lane = tid & 31;
        const float* hp = h2 + w*216;
        float s = 0.f;
        #pragma unroll
        for (int idx = lane; idx < 216; idx += 32)
            s += hp[idx];
        #pragma unroll
        for (int off = 16; off; off >>= 1)
            s += __shfl_down_sync(0xffffffffu, s, off);
        if (lane == 0) g_feat[n*16 + w] = s;
    }

    // Fused final: last CTA does maxpool + linear
    __threadfence();
    __syncthreads();
    if (tid == 0) {
        unsigned old = atomicAdd(&g_ctr, 1u);
        s_last = (old == (unsigned)(gridDim.x - 1)) ? 1u : 0u;
    }
    __syncthreads();
    if (s_last) {
        __threadfence();
        float* sp = A;
        float* pooled = A + 512;
        for (int b = 0; b < 4; b++) {
            int o = tid & 15, grp = tid >> 4;
            float m = -3.4e38f;
            #pragma unroll
            for (int j = 0; j < 16; j++) {
                int p = grp + j*32;
                m = fmaxf(m, g_feat[(b*512 + p)*16 + o]);
            }
            sp[grp*16 + o] = m;
            __syncthreads();
            if (tid < 16) {
                float mm = sp[tid];
                for (int g2 = 1; g2 < 32; g2++) mm = fmaxf(mm, sp[g2*16 + tid]);
                pooled[tid] = mm;
            }
            __syncthreads();
            if (tid < 10) {
                float acc = b_out[tid];
                #pragma unroll
                for (int o2 = 0; o2 < 16; o2++) acc += pooled[o2]*w_out[tid*16 + o2];
                out[b*10 + tid] = acc;
            }
            __syncthreads();
        }
        if (tid == 0) g_ctr = 0;
    }
}

extern "C" void kernel_launch(void* const* d_in, const int* in_sizes, int n_in,
                              void* d_out, int out_size) {
    const float* x     = (const float*)d_in[0];
    const float* w1    = (const float*)d_in[1];
    const float* b1    = (const float*)d_in[2];
    const float* w2    = (const float*)d_in[3];
    const float* b2    = (const float*)d_in[4];
    const float* w_out = (const float*)d_in[5];
    const float* b_out = (const float*)d_in[6];
    float* out = (float*)d_out;

    cudaFuncSetAttribute(k_forward, cudaFuncAttributeMaxDynamicSharedMemorySize, SM_BYTES);

    k_tables<<<48, 512>>>();
    k_weights<<<20, 512>>>(w1, w2);
    k_forward<<<2048, 512, SM_BYTES>>>(x, b1, b2, w_out, b_out, out);
}

// round 17
// speedup vs baseline: 1.4564x; 1.0109x over previous
#include <cuda_runtime.h>

#define PI_F 3.14159265358979323846f

// exact compile-time twiddles (roots of unity for N=12 and N=6)
#define SQ3_2 0.86602540378443864676f
static __device__ constexpr float CE12X[12] = {1.f, SQ3_2, .5f, 0.f, -.5f, -SQ3_2, -1.f, -SQ3_2, -.5f, 0.f, .5f, SQ3_2};
static __device__ constexpr float CE12Y[12] = {0.f, .5f, SQ3_2, 1.f, SQ3_2, .5f, 0.f, -.5f, -SQ3_2, -1.f, -SQ3_2, -.5f};
static __device__ constexpr float CE6X[6]   = {1.f, .5f, -.5f, -1.f, -.5f, .5f};
static __device__ constexpr float CE6Y[6]   = {0.f, SQ3_2, SQ3_2, 0.f, -SQ3_2, -SQ3_2};
__host__ __device__ constexpr int md(int x, int m) { return ((x % m) + m) % m; }

__constant__ float C_FACTF[11] = {1.f,1.f,2.f,6.f,24.f,120.f,720.f,5040.f,
                                  40320.f,362880.f,3628800.f};

__device__ float  g_w_l2[6];
__device__ float2 g_e20[20], g_e12[12];
__device__ __align__(16) float  g_DS2 [1320];   // [l6][k20][m'+5]  (quad-weighted)
__device__ __align__(16) float  g_TD1C[5184];   // [l6][k12][mq6][j12 pad] *(2l+1), m'>=0 only
__device__ __align__(16) float  g_DSO3[900];    // [l3][k12][m2+2][p2+2] *w
__device__ __align__(16) float  g_TD2 [450];    // [l3][k6][m2+2][p2+2] *(2l+1)
__device__ __align__(16) float2 g_PSI1[1584];   // [l6][g24][m'+5]
__device__ __align__(16) float2 g_PSI2[10800];  // [l3][g144][m+2][p+2]
__device__ __align__(16) float2 g_CY1 [528];    // [l6][o8][p'+5]
__device__ __align__(16) float2 g_CY2 [9600];   // [l3][f8][o16][j2+2][k2+2]
__device__ float  g_feat[2048*16];
__device__ unsigned g_ctr;

__device__ float wig_df(int l, int mp, int m, float beta) {
    if (mp < -l || mp > l || m < -l || m > l) return 0.f;
    float c = cosf(0.5f*beta), s = sinf(0.5f*beta);
    int k0 = max(0, m - mp), k1 = min(l + m, l - mp);
    if (k1 < k0) return 0.f;
    float pre = sqrtf(C_FACTF[l+mp]*C_FACTF[l-mp]*C_FACTF[l+m]*C_FACTF[l-m]);
    float acc = 0.f;
    for (int k = k0; k <= k1; k++) {
        float t = pre/(C_FACTF[l+m-k]*C_FACTF[k]*C_FACTF[mp-m+k]*C_FACTF[l-mp-k]);
        int ec = 2*l - 2*k + m - mp, es = mp - m + 2*k;
        float pc = 1.f, ps = 1.f;
        for (int i = 0; i < ec; i++) pc *= c;
        for (int i = 0; i < es; i++) ps *= s;
        acc += (((mp - m + k) & 1) ? -t : t) * pc * ps;
    }
    return acc;
}

__device__ float quad_w(int k, int b) {   // Driscoll-Healy weight, fp32
    float beta = PI_F*(2*k+1)/(4.0f*b), ss = 0.f;
    for (int j = 0; j < b; j++) ss += sinf((2*j+1)*beta)/(float)(2*j+1);
    return (2.0f/b)*sinf(beta)*ss;
}

__global__ void k_tables() {
    const int N0=1320, N1=5184, N2=900, N3=450, N4=1584, N5=10800, N6=38;
    int stride = gridDim.x * blockDim.x;
    for (int e = blockIdx.x*blockDim.x + threadIdx.x; e < N0+N1+N2+N3+N4+N5+N6; e += stride) {
        int i = e;
        if (i < N0) {
            int j = i%11, k = (i/11)%20, l = i/220;
            g_DS2[i] = wig_df(l, j-5, 0, PI_F*(2*k+1)/40.0f) * quad_w(k, 10);
            continue;
        }
        i -= N0;
        if (i < N1) {  // TD1C[l][k][mq][j12]: m' = mq (0..5), m = j-5
            int j = i%12, mq = (i/12)%6, k = (i/72)%12, l = i/864;
            g_TD1C[i] = (j < 11) ? (float)(2*l+1)*wig_df(l, mq, j-5, PI_F*(2*k+1)/24.0f) : 0.f;
            continue;
        }
        i -= N1;
        if (i < N2) {
            int j = i%5, mi = (i/5)%5, k = (i/25)%12, l = i/300;
            g_DSO3[i] = wig_df(l, mi-2, j-2, PI_F*(2*k+1)/24.0f) * quad_w(k, 6);
            continue;
        }
        i -= N2;
        if (i < N3) {
            int j = i%5, mi = (i/5)%5, k = (i/25)%6, l = i/150;
            g_TD2[i] = (float)(2*l+1) * wig_df(l, mi-2, j-2, PI_F*(2*k+1)/12.0f);
            continue;
        }
        i -= N3;
        if (i < N4) {
            int j = i%11, g = (i/11)%24, l = i/264;
            int mp = j - 5;
            float b  = (float)(g/8 + 1) * (PI_F/24.0f);
            float al = (float)(g%8) * (PI_F/4.0f);
            float d  = wig_df(l, mp, 0, b);
            float ang = -(float)mp * al;
            g_PSI1[i] = make_float2(d*cosf(ang), d*sinf(ang));
            continue;
        }
        i -= N4;
        if (i < N5) {
            int j = i%5, mi = (i/5)%5, g = (i/25)%144, l = i/3600;
            int m = mi - 2, p = j - 2;
            float b  = (float)(g/48 + 1) * (PI_F/24.0f);
            float al = (float)((g/6)%8) * (PI_F/4.0f);
            float ga = (float)(g%6) * (PI_F/3.0f);
            float d  = wig_df(l, m, p, b);
            float ang = -((float)m*al + (float)p*ga);
            g_PSI2[i] = make_float2(d*cosf(ang), d*sinf(ang));
            continue;
        }
        i -= N5;
        if (i < 20)      { float a = 2.0f*PI_F*i/20.0f; g_e20[i] = make_float2(cosf(a), sinf(a)); }
        else if (i < 32) { float a = 2.0f*PI_F*(i-20)/12.0f; g_e12[i-20] = make_float2(cosf(a), sinf(a)); }
        else             g_w_l2[i-32] = quad_w(i-32, 3);
    }
}

__global__ void k_weights(const float* __restrict__ w1, const float* __restrict__ w2) {
    const int NC1 = 528, NC2 = 9600;
    int stride = gridDim.x * blockDim.x;
    for (int e = blockIdx.x*blockDim.x + threadIdx.x; e < NC1+NC2; e += stride) {
        if (e < NC1) {
            int j = e%11, o = (e/11)%8, l = e/88;
            float re = 0.f, im = 0.f;
            for (int g = 0; g < 24; g++) {
                float wv = w1[o*24 + g];
                float2 ps = g_PSI1[(l*24 + g)*11 + j];
                re += wv*ps.x; im += wv*ps.y;
            }
            g_CY1[e] = make_float2(re, -im);
        } else {
            int i = e - NC1;
            int k2 = i%5, j2 = (i/5)%5, o = (i/25)%16, f = (i/400)%8, l = i/3200;
            float re = 0.f, im = 0.f;
            for (int g = 0; g < 144; g++) {
                float wv = w2[(f*16 + o)*144 + g];
                float2 ps = g_PSI2[((l*144 + g)*5 + j2)*5 + k2];
                re += wv*ps.x; im += wv*ps.y;
            }
            g_CY2[i] = make_float2(re, -im);
        }
    }
}

__device__ __forceinline__ float2 cfma(float2 a, float2 b, float2 c) {
    c.x += a.x*b.x - a.y*b.y;
    c.y += a.x*b.y + a.y*b.x;
    return c;
}
__device__ __forceinline__ void cfmac(float2 f, float wx, float wy, float2& c) {
    c.x += f.x*wx - f.y*wy;
    c.y += f.x*wy + f.y*wx;
}

#define SM_FLOATS (256 + 2*13824)
#define SM_BYTES  (SM_FLOATS*4)

// Ph4+5 body: jacc = sum_{l>=mq} TD1C*P (smem), radix-2 gamma synthesis -> G
__device__ __forceinline__ void ph45_body(const float* __restrict__ sTD1,
                                          const float2* __restrict__ P,
                                          float2* __restrict__ G,
                                          int mq, int o, int kk) {
    float2 jacc[12];
    #pragma unroll
    for (int j = 0; j < 12; j++) jacc[j] = make_float2(0.f, 0.f);
    for (int l = mq; l < 6; l++) {
        const float4* dp4 = (const float4*)(sTD1 + ((l*12 + kk)*6 + mq)*12);
        const float4* pp4 = (const float4*)(P + ((l*8 + o)*6 + mq)*12);
        #pragma unroll
        for (int q = 0; q < 3; q++) {
            float4 d  = dp4[q];
            float4 pa = pp4[2*q], pb = pp4[2*q+1];
            jacc[4*q+0].x += d.x*pa.x; jacc[4*q+0].y += d.x*pa.y;
            jacc[4*q+1].x += d.y*pa.z; jacc[4*q+1].y += d.y*pa.w;
            jacc[4*q+2].x += d.z*pb.x; jacc[4*q+2].y += d.z*pb.y;
            jacc[4*q+3].x += d.w*pb.z; jacc[4*q+3].y += d.w*pb.w;
        }
    }
    float2* gp = G + ((o*12 + kk)*6 + mq)*12;
    #pragma unroll
    for (int g1 = 0; g1 < 6; g1++) {
        float2 Se = make_float2(0.f, 0.f), So = make_float2(0.f, 0.f);
        #pragma unroll
        for (int j = 1; j < 11; j += 2)   // p' even
            cfmac(jacc[j], CE12X[md((j-5)*g1,12)], CE12Y[md((j-5)*g1,12)], Se);
        #pragma unroll
        for (int j = 0; j < 11; j += 2)   // p' odd
            cfmac(jacc[j], CE12X[md((j-5)*g1,12)], CE12Y[md((j-5)*g1,12)], So);
        gp[g1]     = make_float2(Se.x + So.x, Se.y + So.y);
        gp[g1 + 6] = make_float2(Se.x - So.x, Se.y - So.y);
    }
}

__global__ void __launch_bounds__(512, 2)
k_forward(const float* __restrict__ x, const float* __restrict__ b1,
          const float* __restrict__ b2, const float* __restrict__ w_out,
          const float* __restrict__ b_out, float* __restrict__ out) {
    extern __shared__ float sm[];
    float2* se20 = (float2*)(sm);        // 20c
    float2* se12 = (float2*)(sm + 40);   // 12c
    float*  sb1  = sm + 76;              // 8
    float*  sb2  = sm + 84;              // 16
    float*  swi  = sm + 100;             // 6
    float*  A    = sm + 256;
    float*  Bb   = sm + 256 + 13824;
    __shared__ unsigned s_last;

    const int tid = threadIdx.x;
    const int n = blockIdx.x;

    if (tid < 20)                se20[tid]     = g_e20[tid];
    if (tid >= 32  && tid < 44)  se12[tid-32]  = g_e12[tid-32];
    if (tid >= 96  && tid < 104) sb1 [tid-96]  = b1[tid-96];
    if (tid >= 128 && tid < 144) sb2 [tid-128] = b2[tid-128];
    if (tid >= 160 && tid < 166) swi [tid-160] = g_w_l2[tid-160] * (1.f/36.f);
    __syncthreads();

    // Ph1: alpha analysis Xf[k][m'+5] (B) straight from global x.
    // Idle threads stage TD1C into A[6912..12096).
    float2* Xf = (float2*)Bb;
    float* sTD1 = A + 6912;
    if (tid < 220) {
        int k = tid/11, mp = tid%11 - 5;
        int s = (20 - mp) % 20;
        const float* xp = x + n*400 + k*20;
        float re = 0.f, im = 0.f;
        int r = 0;
        #pragma unroll
        for (int a = 0; a < 20; a++) {
            float v = xp[a];
            float2 w = se20[r];
            re += v*w.x; im += v*w.y;
            r += s; if (r >= 20) r -= 20;
        }
        Xf[tid] = make_float2(re, im);
    } else if (tid >= 256) {
        float4* dst = (float4*)sTD1;
        const float4* src = (const float4*)g_TD1C;
        for (int i = tid - 256; i < 1296; i += 256) dst[i] = src[i];
    }
    __syncthreads();

    // Ph2+3 merged: each (l,o,mq) thread computes its own XS value then CY1 -> P (A)
    float2* P = (float2*)A;
    if (tid < 288) {
        int mq = tid % 6, o = (tid/6) % 8, l = tid/48;
        int j = mq + 5;
        float2 xs = make_float2(0.f, 0.f);
        #pragma unroll
        for (int k = 0; k < 20; k++) {
            float d = g_DS2[(l*20 + k)*11 + j];
            float2 v = Xf[k*11 + j];
            xs.x += d*v.x; xs.y += d*v.y;
        }
        const float2* cy = g_CY1 + (l*8 + o)*11;
        float2* op = P + ((l*8 + o)*6 + mq)*12;
        #pragma unroll
        for (int jj = 0; jj < 11; jj++) {
            float2 c = cy[jj];
            op[jj] = make_float2(xs.x*c.x - xs.y*c.y, xs.x*c.y + xs.y*c.x);
        }
        op[11] = make_float2(0.f, 0.f);
    }
    __syncthreads();

    // Ph4+5 fused, BALANCED: threads 0-479 one item each (mq = tid/96);
    // threads 384-479 (first item mq=4, cheap) also take one mq=5 item each.
    float2* G = (float2*)Bb;
    if (tid < 480) {
        int mq = tid / 96;
        int r  = tid % 96;
        ph45_body(sTD1, P, G, mq, r/12, r%12);
        if (tid >= 384) {
            int r2 = tid - 384;        // items 480..575, all mq=5
            ph45_body(sTD1, P, G, 5, r2/12, r2%12);
        }
    }
    __syncthreads();

    // Ph6: alpha synthesis (Hermitian, radix-2) + bias + ReLU -> h1[f][k][a][g] (A)
    float* h1 = A;
    for (int t = tid; t < 1152; t += 512) {
        int g = t % 12, kk = (t/12) % 12, f = t/144;
        const float2* Gp = G + (f*12 + kk)*72 + g;
        float2 gm1 = Gp[12], gm2 = Gp[24], gm3 = Gp[36], gm4 = Gp[48], gm5 = Gp[60];
        float g0 = Gp[0].x;
        float bb = sb1[f];
        float* op = h1 + ((f*12 + kk)*12)*12 + g;
        #pragma unroll
        for (int a1 = 0; a1 < 6; a1++) {
            float E = g0
                + 2.f*(gm2.x*CE12X[md(2*a1,12)] - gm2.y*CE12Y[md(2*a1,12)])
                + 2.f*(gm4.x*CE12X[md(4*a1,12)] - gm4.y*CE12Y[md(4*a1,12)]);
            float O =
                  2.f*(gm1.x*CE12X[md(a1,12)]   - gm1.y*CE12Y[md(a1,12)])
                + 2.f*(gm3.x*CE12X[md(3*a1,12)] - gm3.y*CE12Y[md(3*a1,12)])
                + 2.f*(gm5.x*CE12X[md(5*a1,12)] - gm5.y*CE12Y[md(5*a1,12)]);
            op[a1*12]       = fmaxf(E + O + bb, 0.f);
            op[(a1 + 6)*12] = fmaxf(E - O + bb, 0.f);
        }
    }
    __syncthreads();

    // Ph7: gamma analysis T[f][k][a][p2] (B). Radix-2 in g.
    float2* T = (float2*)Bb;
    for (int t = tid; t < 1152; t += 512) {
        int a = t % 12, kk = (t/12) % 12, f = t/144;
        const float4* hp4 = (const float4*)(h1 + ((f*12 + kk)*12 + a)*12);
        float h[12];
        #pragma unroll
        for (int q = 0; q < 3; q++) {
            float4 v = hp4[q];
            h[4*q] = v.x; h[4*q+1] = v.y; h[4*q+2] = v.z; h[4*q+3] = v.w;
        }
        float he[6], ho[6];
        #pragma unroll
        for (int g1 = 0; g1 < 6; g1++) { he[g1] = h[g1] + h[g1+6]; ho[g1] = h[g1] - h[g1+6]; }
        float2* op = T + ((f*12 + kk)*12 + a)*3;
        op[0] = make_float2(he[0]+he[1]+he[2]+he[3]+he[4]+he[5], 0.f);
        {
            float re = 0.f, im = 0.f;
            #pragma unroll
            for (int g1 = 0; g1 < 6; g1++) {
                re += ho[g1]*CE12X[g1];
                im -= ho[g1]*CE12Y[g1];
            }
            op[1] = make_float2(re, im);
        }
        {
            float re = 0.f, im = 0.f;
            #pragma unroll
            for (int g1 = 0; g1 < 6; g1++) {
                re += he[g1]*CE12X[md(2*g1,12)];
                im -= he[g1]*CE12Y[md(2*g1,12)];
            }
            op[2] = make_float2(re, im);
        }
    }
    __syncthreads();

    // Ph8: alpha analysis F2h[f][k][m2][p2+2] (A), only m2 = 0..2 (i2 = 2..4)
    float2* F2h = (float2*)A;
    if (tid < 288) {
        int m2 = tid % 3, kk = (tid/3) % 12, f = tid/36;
        int i2 = m2 + 2;
        int s = (12 - m2) % 12;
        float2 acc[5];
        #pragma unroll
        for (int j = 0; j < 5; j++) acc[j] = make_float2(0.f, 0.f);
        const float2* Tp = T + ((f*12 + kk)*12)*3;
        int r = 0;
        #pragma unroll
        for (int a = 0; a < 12; a++) {
            float2 t0 = Tp[a*3+0], t1 = Tp[a*3+1], t2 = Tp[a*3+2];
            float2 tw = se12[r];
            acc[0] = cfma(make_float2(t2.x, -t2.y), tw, acc[0]);
            acc[1] = cfma(make_float2(t1.x, -t1.y), tw, acc[1]);
            acc[2] = cfma(t0, tw, acc[2]);
            acc[3] = cfma(t1, tw, acc[3]);
            acc[4] = cfma(t2, tw, acc[4]);
            r += s; if (r >= 12) r -= 12;
        }
        float2* op = F2h + ((f*12 + kk)*5 + i2)*5;
        #pragma unroll
        for (int j = 0; j < 5; j++) op[j] = acc[j];
    }
    __syncthreads();

    // Ph9: XS2[l][f][i2][k2] = sum_k F2h * DSO3 (B). One output/thread (360).
    float2* XS2 = (float2*)Bb;
    if (tid < 360) {
        int k2 = tid % 5;
        int rr = tid / 5;
        int i2 = rr % 3 + 2, f = (rr/3) % 8, l = rr/24;
        float2 acc = make_float2(0.f, 0.f);
        #pragma unroll
        for (int k = 0; k < 12; k++) {
            float d = g_DSO3[((l*12 + k)*5 + i2)*5 + k2];
            float2 v = F2h[((f*12 + k)*5 + i2)*5 + k2];
            acc.x += d*v.x; acc.y += d*v.y;
        }
        XS2[(l*8 + f)*25 + i2*5 + k2] = acc;
    }
    __syncthreads();

    // Ph10: warp-cooperative Z2[l][o][i2][j2] (A), only i2 = 2..4.
    float2* Z2 = (float2*)A;
    {
        int w = tid >> 5, lane = tid & 31;
        int j2 = lane / 5, k2 = lane % 5;
        int cl = (lane < 25) ? lane : 24;
        #pragma unroll
        for (int it = 0; it < 3; it++) {
            int idx = it*16 + w;          // 0..47
            int l = idx >> 4, o = idx & 15;
            float2 acc[3];
            #pragma unroll
            for (int q = 0; q < 3; q++) acc[q] = make_float2(0.f, 0.f);
            #pragma unroll
            for (int f = 0; f < 8; f++) {
                float2 cy = g_CY2[((l*8 + f)*16 + o)*25 + cl];
                const float2* xb = XS2 + (l*8 + f)*25 + k2;
                #pragma unroll
                for (int q = 0; q < 3; q++)
                    acc[q] = cfma(xb[(q+2)*5], cy, acc[q]);
            }
            #pragma unroll
            for (int q = 0; q < 3; q++) {
                float rx = acc[q].x, ry = acc[q].y;
                #pragma unroll
                for (int d = 1; d < 5; d++) {
                    rx += __shfl_down_sync(0xffffffffu, acc[q].x, d);
                    ry += __shfl_down_sync(0xffffffffu, acc[q].y, d);
                }
                if (k2 == 0 && j2 < 5)
                    Z2[((l*16 + o)*5 + (q+2))*5 + j2] = make_float2(rx, ry);
            }
        }
    }
    __syncthreads();

    // Ph11 fused: jacc = sum_{l>=mq} TD2*Z2 (regs), radix-2 gamma synthesis -> G2 (B)
    float2* G2 = (float2*)Bb;
    if (tid < 288) {
        int mq = tid / 96;
        int r  = tid % 96;
        int o  = r / 6, kk = r % 6;
        float2 jacc[5];
        #pragma unroll
        for (int j = 0; j < 5; j++) jacc[j] = make_float2(0.f, 0.f);
        for (int l = mq; l < 3; l++) {
            const float* dp = g_TD2 + ((l*6 + kk)*5 + (mq+2))*5;
            const float2* zp = Z2 + ((l*16 + o)*5 + (mq+2))*5;
            #pragma unroll
            for (int j = 0; j < 5; j++) {
                float d = dp[j];
                jacc[j].x += d*zp[j].x; jacc[j].y += d*zp[j].y;
            }
        }
        float2* gp = G2 + ((o*6 + kk)*3 + mq)*6;
        #pragma unroll
        for (int g1 = 0; g1 < 3; g1++) {
            float2 Se = make_float2(0.f, 0.f), So = make_float2(0.f, 0.f);
            cfmac(jacc[0], CE6X[md(-2*g1,6)], CE6Y[md(-2*g1,6)], Se);
            Se.x += jacc[2].x; Se.y += jacc[2].y;
            cfmac(jacc[4], CE6X[md(2*g1,6)], CE6Y[md(2*g1,6)], Se);
            cfmac(jacc[1], CE6X[md(-g1,6)], CE6Y[md(-g1,6)], So);
            cfmac(jacc[3], CE6X[md(g1,6)],  CE6Y[md(g1,6)],  So);
            gp[g1]     = make_float2(Se.x + So.x, Se.y + So.y);
            gp[g1 + 3] = make_float2(Se.x - So.x, Se.y - So.y);
        }
    }
    __syncthreads();

    // Ph12: alpha synthesis (Hermitian) + bias + ReLU, a-summed & weighted -> hsum (A)
    // hsum[o*36 + kk*6 + g] = wk * sum_a relu(v(a) + b)
    float* hsum = A;
    for (int t = tid; t < 576; t += 512) {
        int g = t % 6, kk = (t/6) % 6, o = t/36;
        const float2* Gp = G2 + (o*6 + kk)*18 + g;
        float2 g0 = Gp[0], g1 = Gp[6], g2 = Gp[12];
        float g1x = 2.f*g1.x, g1y = 2.f*g1.y, g2x = 2.f*g2.x, g2y = 2.f*g2.y;
        float bb = sb2[o];
        float wk = swi[kk];
        float s = 0.f;
        #pragma unroll
        for (int a = 0; a < 6; a++) {
            float v = g0.x + g1x*CE6X[md(a,6)] - g1y*CE6Y[md(a,6)]
                           + g2x*CE6X[md(2*a,6)] - g2y*CE6Y[md(2*a,6)];
            s += fmaxf(v + bb, 0.f);
        }
        hsum[o*36 + kk*6 + g] = s * wk;
    }
    __syncthreads();

    // Ph13: feat[n][o] = sum of 36 hsum values per o (warp o = w)
    {
        int w = tid >> 5, lane = tid & 31;
        const float* hp = hsum + w*36;
        float s = hp[lane] + ((lane < 4) ? hp[32 + lane] : 0.f);
        #pragma unroll
        for (int off = 16; off; off >>= 1)
            s += __shfl_down_sync(0xffffffffu, s, off);
        if (lane == 0) g_feat[n*16 + w] = s;
    }

    // Fused final: last CTA does maxpool + linear
    __threadfence();
    __syncthreads();
    if (tid == 0) {
        unsigned old = atomicAdd(&g_ctr, 1u);
        s_last = (old == (unsigned)(gridDim.x - 1)) ? 1u : 0u;
    }
    __syncthreads();
    if (s_last) {
        __threadfence();
        float* sp = A;
        float* pooled = A + 512;
        for (int b = 0; b < 4; b++) {
            int o = tid & 15, grp = tid >> 4;
            float m = -3.4e38f;
            #pragma unroll
            for (int j = 0; j < 16; j++) {
                int p = grp + j*32;
                m = fmaxf(m, g_feat[(b*512 + p)*16 + o]);
            }
            sp[grp*16 + o] = m;
            __syncthreads();
            if (tid < 16) {
                float mm = sp[tid];
                for (int g2 = 1; g2 < 32; g2++) mm = fmaxf(mm, sp[g2*16 + tid]);
                pooled[tid] = mm;
            }
            __syncthreads();
            if (tid < 10) {
                float acc = b_out[tid];
                #pragma unroll
                for (int o2 = 0; o2 < 16; o2++) acc += pooled[o2]*w_out[tid*16 + o2];
                out[b*10 + tid] = acc;
            }
            __syncthreads();
        }
        if (tid == 0) g_ctr = 0;
    }
}

extern "C" void kernel_launch(void* const* d_in, const int* in_sizes, int n_in,
                              void* d_out, int out_size) {
    const float* x     = (const float*)d_in[0];
    const float* w1    = (const float*)d_in[1];
    const float* b1    = (const float*)d_in[2];
    const float* w2    = (const float*)d_in[3];
    const float* b2    = (const float*)d_in[4];
    const float* w_out = (const float*)d_in[5];
    const float* b_out = (const float*)d_in[6];
    float* out = (float*)d_out;

    cudaFuncSetAttribute(k_forward, cudaFuncAttributeMaxDynamicSharedMemorySize, SM_BYTES);

    k_tables<<<160, 128>>>();
    k_weights<<<80, 128>>>(w1, w2);
    k_forward<<<2048, 512, SM_BYTES>>>(x, b1, b2, w_out, b_out, out);
}